// round 6
// baseline (speedup 1.0000x reference)
#include <cuda_runtime.h>
#include <cstdint>
#include <math.h>

// ---------------------------------------------------------------------------
// MultiHeadAttention, tf32 mma.sync GEMMs, cp.async 3-stage pipelines,
// fused softmax (exp + rowsum in QK^T epilogue, normalize in AV).
// CTA tile 128x128x32, warp tile 64x32, 2 CTAs/SM (16 warps/SM).
// d_out = y [S,F] then attn [8,S,S] (fp32). S=4096, F=H=1024, dk=128.
// ---------------------------------------------------------------------------

#define SMAX 4096
#define HMAX 1024
#define NHEAD 8

__device__ float g_q[SMAX * HMAX];
__device__ float g_k[SMAX * HMAX];
__device__ float g_v[SMAX * HMAX];
__device__ float g_y[SMAX * HMAX];
__device__ float g_rs[NHEAD * SMAX];   // row sums of exp -> inverted in place

__device__ __forceinline__ unsigned tf32u(unsigned x) {
    unsigned r;
    asm("cvt.rna.tf32.f32 %0, %1;" : "=r"(r) : "f"(__uint_as_float(x)));
    return r;
}
__device__ __forceinline__ void mma_tf32(float* c, const unsigned* a, const unsigned* b) {
    asm volatile(
        "mma.sync.aligned.m16n8k8.row.col.f32.tf32.tf32.f32 "
        "{%0,%1,%2,%3}, {%4,%5,%6,%7}, {%8,%9}, {%0,%1,%2,%3};"
        : "+f"(c[0]), "+f"(c[1]), "+f"(c[2]), "+f"(c[3])
        : "r"(a[0]), "r"(a[1]), "r"(a[2]), "r"(a[3]), "r"(b[0]), "r"(b[1]));
}
__device__ __forceinline__ uint32_t smem_u32(const void* p) {
    uint32_t a;
    asm("{ .reg .u64 t; cvta.to.shared.u64 t, %1; cvt.u32.u64 %0, t; }" : "=r"(a) : "l"(p));
    return a;
}
__device__ __forceinline__ void cp16(uint32_t s, const void* g) {
    asm volatile("cp.async.cg.shared.global [%0], [%1], 16;" :: "r"(s), "l"(g));
}
#define CP_COMMIT() asm volatile("cp.async.commit_group;")
#define CP_WAIT1()  asm volatile("cp.async.wait_group 1;")
#define CP_WAIT0()  asm volatile("cp.async.wait_group 0;")

// Tile config: CTA 128(M) x 128(N) x 32(K), 8 warps (2m x 4n), warp tile 64x32.
#define MT  128
#define NT  128
#define BK  32
#define STAGES 3
#define AS_STRIDE 36      // floats; [m][k] / TB [n][k]
#define BS_STRIDE 136     // NN layout [k][n]
#define A_BYTES  (128 * AS_STRIDE * 4)           // 18432
#define B_BYTES  (128 * AS_STRIDE * 4)           // 18432 (covers NN 17408 too)
#define STAGE_BYTES (A_BYTES + B_BYTES)          // 36864
#define SMEM_DYN (STAGES * STAGE_BYTES)          // 110592

// ---------------------------------------------------------------------------
// TB=false: C = alpha * A[M,K] @ B[K,N]   (B row-major; Bs [k][n] stride 136)
// TB=true : C = alpha * A[M,K] @ B[N,K]^T (B K-major;   Bs [n][k] stride 36)
// EXPE    : epilogue C = exp(alpha*acc), atomicAdd row sums into rs
// NORM    : A loaded via LDG, scaled by rs[row] (pre-inverted), scaled value
//           written back to Aw (attn normalization), fp32 into smem.
// Consumer applies cvt.rna.tf32 to every fragment before mma.
// ---------------------------------------------------------------------------
template <bool TB, bool EXPE, bool NORM>
__global__ void __launch_bounds__(256, 2) gemm_mha(
    const float* __restrict__ A, const float* __restrict__ B, float* __restrict__ C,
    float* __restrict__ Aw, float* __restrict__ rs,
    int K, int lda, int ldb, int ldc,
    long long sA, long long sB, long long sC, float alpha, int S)
{
    extern __shared__ char smem[];
    const uint32_t sbase = smem_u32(smem);
    const int tid = threadIdx.x;
    const int lane = tid & 31;
    const int warp = tid >> 5;
    const int lg = lane >> 2;          // 0..7
    const int l4 = lane & 3;           // 0..3
    const int wm = (warp & 1) * 64;    // 2 m-warps
    const int wn = (warp >> 1) * 32;   // 4 n-warps

    const int m0 = blockIdx.y * MT;
    const int n0 = blockIdx.x * NT;

    const float* Ab = A + (long long)blockIdx.z * sA + (long long)m0 * lda;
    float* Awb = NORM ? (Aw + (long long)blockIdx.z * sA + (long long)m0 * lda) : nullptr;
    const float* Bb;
    if (TB) Bb = B + (long long)blockIdx.z * sB + (long long)n0 * ldb;
    else    Bb = B + (long long)blockIdx.z * sB + n0;
    float* Cb = C + (long long)blockIdx.z * sC + (long long)m0 * ldc + n0;

    // loader mappings (A tile and TB-B tile: 128 rows x 32 floats, 4 cp16/thread)
    const int a_r = tid >> 2;            // 0..63 (+64)
    const int a_c = (tid & 3) * 4;       // float col base; +16 for second chunk
    // B NN: 32 k-rows x 128 floats, 4 cp16/thread
    const int bn_k = tid >> 3;           // 0..31
    const int bn_c = (tid & 7) * 4;      // +32j

    float inv[2];
    if (NORM) {
        inv[0] = rs[blockIdx.z * S + m0 + a_r];
        inv[1] = rs[blockIdx.z * S + m0 + a_r + 64];
    }

    float acc[4][4][4];
#pragma unroll
    for (int mt = 0; mt < 4; mt++)
#pragma unroll
        for (int nt = 0; nt < 4; nt++)
#pragma unroll
            for (int i = 0; i < 4; i++) acc[mt][nt][i] = 0.0f;

    const int ktiles = K / BK;
    float4 pa[4];   // only used when NORM

    auto issueA = [&](int st, int kt) {
        const uint32_t as = sbase + st * STAGE_BYTES;
        const float* p = Ab + (long long)a_r * lda + kt * BK + a_c;
#pragma unroll
        for (int i = 0; i < 2; i++)
#pragma unroll
            for (int j = 0; j < 2; j++)
                cp16(as + (uint32_t)(((a_r + 64 * i) * AS_STRIDE + a_c + 16 * j) * 4),
                     p + (long long)(64 * i) * lda + 16 * j);
    };
    auto issueB = [&](int st, int kt) {
        const uint32_t bs = sbase + st * STAGE_BYTES + A_BYTES;
        if (TB) {
            const float* p = Bb + (long long)a_r * ldb + kt * BK + a_c;
#pragma unroll
            for (int i = 0; i < 2; i++)
#pragma unroll
                for (int j = 0; j < 2; j++)
                    cp16(bs + (uint32_t)(((a_r + 64 * i) * AS_STRIDE + a_c + 16 * j) * 4),
                         p + (long long)(64 * i) * ldb + 16 * j);
        } else {
            const float* p = Bb + (long long)(kt * BK + bn_k) * ldb + bn_c;
#pragma unroll
            for (int j = 0; j < 4; j++)
                cp16(bs + (uint32_t)((bn_k * BS_STRIDE + bn_c + 32 * j) * 4),
                     p + 32 * j);
        }
    };
    auto ldAreg = [&](int kt) {
        const float* p = Ab + (long long)a_r * lda + kt * BK + a_c;
#pragma unroll
        for (int i = 0; i < 2; i++)
#pragma unroll
            for (int j = 0; j < 2; j++)
                pa[i * 2 + j] = *(const float4*)(p + (long long)(64 * i) * lda + 16 * j);
    };
    auto stAnorm = [&](int st, int kt) {
        float* As = (float*)(smem + st * STAGE_BYTES);
#pragma unroll
        for (int i = 0; i < 2; i++)
#pragma unroll
            for (int j = 0; j < 2; j++) {
                float4 v = pa[i * 2 + j];
                v.x *= inv[i]; v.y *= inv[i]; v.z *= inv[i]; v.w *= inv[i];
                *(float4*)(Awb + (long long)(a_r + 64 * i) * lda + kt * BK + a_c + 16 * j) = v;
                *(float4*)&As[(a_r + 64 * i) * AS_STRIDE + a_c + 16 * j] = v;
            }
    };

    // ---- prologue: fill stages 0,1 ----
#pragma unroll
    for (int s = 0; s < 2; s++) {
        if (!NORM) issueA(s, s);
        issueB(s, s);
        CP_COMMIT();
        if (NORM) { ldAreg(s); stAnorm(s, s); }
    }

    for (int kt = 0; kt < ktiles; kt++) {
        const int cur = kt % STAGES;
        const bool has = (kt + 2 < ktiles);
        if (has) CP_WAIT1(); else CP_WAIT0();
        __syncthreads();

        const int nx = (kt + 2) % STAGES;
        if (has) {
            if (!NORM) issueA(nx, kt + 2);
            issueB(nx, kt + 2);
            CP_COMMIT();
            if (NORM) ldAreg(kt + 2);
        }

        const float* As = (const float*)(smem + cur * STAGE_BYTES);
        const float* Bs = (const float*)(smem + cur * STAGE_BYTES + A_BYTES);
#pragma unroll
        for (int ks = 0; ks < 4; ks++) {
            const int k = ks * 8;
            unsigned a[4][4], b[4][2];
#pragma unroll
            for (int mt = 0; mt < 4; mt++) {
                const int r = wm + mt * 16 + lg;
                a[mt][0] = tf32u(__float_as_uint(As[r * AS_STRIDE + k + l4]));
                a[mt][1] = tf32u(__float_as_uint(As[(r + 8) * AS_STRIDE + k + l4]));
                a[mt][2] = tf32u(__float_as_uint(As[r * AS_STRIDE + k + l4 + 4]));
                a[mt][3] = tf32u(__float_as_uint(As[(r + 8) * AS_STRIDE + k + l4 + 4]));
            }
#pragma unroll
            for (int nt = 0; nt < 4; nt++) {
                const int c = wn + nt * 8 + lg;
                if (TB) {
                    b[nt][0] = tf32u(__float_as_uint(Bs[c * AS_STRIDE + k + l4]));
                    b[nt][1] = tf32u(__float_as_uint(Bs[c * AS_STRIDE + k + l4 + 4]));
                } else {
                    b[nt][0] = tf32u(__float_as_uint(Bs[(k + l4) * BS_STRIDE + c]));
                    b[nt][1] = tf32u(__float_as_uint(Bs[(k + l4 + 4) * BS_STRIDE + c]));
                }
            }
#pragma unroll
            for (int mt = 0; mt < 4; mt++)
#pragma unroll
                for (int nt = 0; nt < 4; nt++)
                    mma_tf32(acc[mt][nt], a[mt], b[nt]);
        }

        if (has && NORM) stAnorm(nx, kt + 2);
    }

    // ---- epilogue ----
    if (EXPE) {
        float ps[4][2];
#pragma unroll
        for (int mt = 0; mt < 4; mt++) { ps[mt][0] = 0.0f; ps[mt][1] = 0.0f; }
#pragma unroll
        for (int mt = 0; mt < 4; mt++) {
            const int r = wm + mt * 16 + lg;
#pragma unroll
            for (int nt = 0; nt < 4; nt++) {
                const int c = wn + nt * 8 + 2 * l4;
                float e0 = __expf(acc[mt][nt][0] * alpha);
                float e1 = __expf(acc[mt][nt][1] * alpha);
                float e2 = __expf(acc[mt][nt][2] * alpha);
                float e3 = __expf(acc[mt][nt][3] * alpha);
                *(float2*)(Cb + (long long)r * ldc + c) = make_float2(e0, e1);
                *(float2*)(Cb + (long long)(r + 8) * ldc + c) = make_float2(e2, e3);
                ps[mt][0] += e0 + e1;
                ps[mt][1] += e2 + e3;
            }
        }
#pragma unroll
        for (int mt = 0; mt < 4; mt++) {
#pragma unroll
            for (int h = 0; h < 2; h++) {
                float v = ps[mt][h];
                v += __shfl_xor_sync(0xffffffffu, v, 1);
                v += __shfl_xor_sync(0xffffffffu, v, 2);
                if (l4 == 0)
                    atomicAdd(&rs[blockIdx.z * S + m0 + wm + mt * 16 + lg + h * 8], v);
            }
        }
    } else {
#pragma unroll
        for (int mt = 0; mt < 4; mt++) {
            const int r = wm + mt * 16 + lg;
#pragma unroll
            for (int nt = 0; nt < 4; nt++) {
                const int c = wn + nt * 8 + 2 * l4;
                *(float2*)(Cb + (long long)r * ldc + c) =
                    make_float2(acc[mt][nt][0] * alpha, acc[mt][nt][1] * alpha);
                *(float2*)(Cb + (long long)(r + 8) * ldc + c) =
                    make_float2(acc[mt][nt][2] * alpha, acc[mt][nt][3] * alpha);
            }
        }
    }
}

__global__ void zero_rs(float* rs, int n) {
    int i = blockIdx.x * blockDim.x + threadIdx.x;
    if (i < n) rs[i] = 0.0f;
}
__global__ void inv_rs(float* rs, int n) {
    int i = blockIdx.x * blockDim.x + threadIdx.x;
    if (i < n) rs[i] = 1.0f / rs[i];
}

extern "C" void kernel_launch(void* const* d_in, const int* in_sizes, int n_in,
                              void* d_out, int out_size)
{
    const float* x  = (const float*)d_in[0];
    const float* Wq = (const float*)d_in[1];
    const float* Wk = (const float*)d_in[2];
    const float* Wv = (const float*)d_in[3];
    const float* Wo = (const float*)d_in[4];

    const int F  = 1024;
    const int H  = 1024;
    const int NH = NHEAD;
    const int DK = H / NH;                 // 128
    const int S  = in_sizes[0] / F;        // 4096

    float* y_out    = (float*)d_out;
    float* attn_out = y_out + (long long)S * H;

    float *q, *k, *v, *y, *rs;
    cudaGetSymbolAddress((void**)&q, g_q);
    cudaGetSymbolAddress((void**)&k, g_k);
    cudaGetSymbolAddress((void**)&v, g_v);
    cudaGetSymbolAddress((void**)&y, g_y);
    cudaGetSymbolAddress((void**)&rs, g_rs);

    cudaFuncSetAttribute(gemm_mha<false, false, false>,
                         cudaFuncAttributeMaxDynamicSharedMemorySize, SMEM_DYN);
    cudaFuncSetAttribute(gemm_mha<true, true, false>,
                         cudaFuncAttributeMaxDynamicSharedMemorySize, SMEM_DYN);
    cudaFuncSetAttribute(gemm_mha<false, false, true>,
                         cudaFuncAttributeMaxDynamicSharedMemorySize, SMEM_DYN);

    const dim3 blk(256);
    const float inv_sqrt_dk = 0.08838834764831845f;  // 1/sqrt(128)

    // 0) zero row sums (graph-replay safe)
    zero_rs<<<(NH * S + 255) / 256, 256>>>(rs, NH * S);

    // 1) Q/K/V projections: [S,F] @ [F,H]
    dim3 g1(H / NT, S / MT, 1);
    gemm_mha<false, false, false><<<g1, blk, SMEM_DYN>>>(
        x, Wq, q, nullptr, rs, F, F, H, H, 0, 0, 0, 1.0f, S);
    gemm_mha<false, false, false><<<g1, blk, SMEM_DYN>>>(
        x, Wk, k, nullptr, rs, F, F, H, H, 0, 0, 0, 1.0f, S);
    gemm_mha<false, false, false><<<g1, blk, SMEM_DYN>>>(
        x, Wv, v, nullptr, rs, F, F, H, H, 0, 0, 0, 1.0f, S);

    // 2) logits -> exp(Q K^T / sqrt(dk)) into attn region + row sums
    dim3 g2(S / NT, S / MT, NH);
    gemm_mha<true, true, false><<<g2, blk, SMEM_DYN>>>(
        q, k, attn_out, nullptr, rs, DK, H, H, S,
        (long long)DK, (long long)DK, (long long)S * S, inv_sqrt_dk, S);

    // 3) invert row sums
    inv_rs<<<(NH * S + 255) / 256, 256>>>(rs, NH * S);

    // 4) AV: normalize attn on load (writing normalized attn back), Y = attn@V
    dim3 g3(DK / NT, S / MT, NH);
    gemm_mha<false, false, true><<<g3, blk, SMEM_DYN>>>(
        attn_out, v, y, attn_out, rs, S, S, H, H,
        (long long)S * S, (long long)DK, (long long)DK, 1.0f, S);

    // 5) output projection: y_out = Y @ Wo
    dim3 g4(F / NT, S / MT, 1);
    gemm_mha<false, false, false><<<g4, blk, SMEM_DYN>>>(
        y, Wo, y_out, nullptr, rs, H, H, F, F, 0, 0, 0, 1.0f, S);
}

// round 7
// speedup vs baseline: 1.1052x; 1.1052x over previous
#include <cuda_runtime.h>
#include <cstdint>
#include <math.h>

// ---------------------------------------------------------------------------
// MultiHeadAttention, tf32 mma.sync GEMMs, cp.async 4-stage pipelines,
// fused softmax. Operands pre-rounded to tf32 at producer epilogues so the
// hot GEMM mainloops need no cvt (mma RZ-truncation of tf32 values is exact).
// d_out = y [S,F] then attn [8,S,S] (fp32). S=4096, F=H=1024, dk=128.
// ---------------------------------------------------------------------------

#define SMAX 4096
#define HMAX 1024
#define NHEAD 8

__device__ float g_q[SMAX * HMAX];
__device__ float g_k[SMAX * HMAX];
__device__ float g_v[SMAX * HMAX];
__device__ float g_y[SMAX * HMAX];
__device__ float g_rs[NHEAD * SMAX];   // row sums of exp -> inverted in place

__device__ __forceinline__ unsigned tf32u(unsigned x) {
    unsigned r;
    asm("cvt.rna.tf32.f32 %0, %1;" : "=r"(r) : "f"(__uint_as_float(x)));
    return r;
}
__device__ __forceinline__ float tf32f(float x) {
    unsigned r;
    asm("cvt.rna.tf32.f32 %0, %1;" : "=r"(r) : "f"(x));
    return __uint_as_float(r);
}
__device__ __forceinline__ void mma_tf32(float* c, const unsigned* a, const unsigned* b) {
    asm volatile(
        "mma.sync.aligned.m16n8k8.row.col.f32.tf32.tf32.f32 "
        "{%0,%1,%2,%3}, {%4,%5,%6,%7}, {%8,%9}, {%0,%1,%2,%3};"
        : "+f"(c[0]), "+f"(c[1]), "+f"(c[2]), "+f"(c[3])
        : "r"(a[0]), "r"(a[1]), "r"(a[2]), "r"(a[3]), "r"(b[0]), "r"(b[1]));
}
__device__ __forceinline__ uint32_t smem_u32(const void* p) {
    uint32_t a;
    asm("{ .reg .u64 t; cvta.to.shared.u64 t, %1; cvt.u32.u64 %0, t; }" : "=r"(a) : "l"(p));
    return a;
}
__device__ __forceinline__ void cp16(uint32_t s, const void* g) {
    asm volatile("cp.async.cg.shared.global [%0], [%1], 16;" :: "r"(s), "l"(g));
}
#define CP_COMMIT() asm volatile("cp.async.commit_group;")
#define CP_WAIT2()  asm volatile("cp.async.wait_group 2;")
#define CP_WAIT1()  asm volatile("cp.async.wait_group 1;")
#define CP_WAIT0()  asm volatile("cp.async.wait_group 0;")

// Tile config: CTA 256(M) x 128(N) x 32(K), 8 warps (4m x 2n), warp tile 64x64.
#define MT  256
#define NT  128
#define BK  32
#define STAGES 4
#define AS_STRIDE 36      // floats; [m][k] and TB [n][k]
#define BS_STRIDE 136     // NN layout [k][n]
#define A_BYTES  (256 * AS_STRIDE * 4)           // 36864
#define B_BYTES  (128 * AS_STRIDE * 4)           // 18432 (covers NN 17408 too)
#define STAGE_BYTES (A_BYTES + B_BYTES)          // 55296
#define SMEM_DYN (STAGES * STAGE_BYTES)          // 221184

// ---------------------------------------------------------------------------
// TB=false: C = alpha * A[M,K] @ B[K,N]   (B row-major; Bs [k][n] stride 136)
// TB=true : C = alpha * A[M,K] @ B[N,K]^T (B K-major;   Bs [n][k] stride 36)
// EXPE : epilogue C = tf32(exp(alpha*acc)), atomicAdd rounded row sums
// NORM : A via LDG (raw tf32-valued e); e*inv written back to Aw (final attn),
//        raw e staged to smem; epilogue scales acc rows by inv.
// CVA/CVB : apply cvt.rna.tf32 to A/B fragments (external fp32 operands only)
// ROUND : round plain epilogue output to tf32 (when C feeds another GEMM)
// ---------------------------------------------------------------------------
template <bool TB, bool EXPE, bool NORM, bool CVA, bool CVB, bool ROUND>
__global__ void __launch_bounds__(256, 1) gemm_mha(
    const float* __restrict__ A, const float* __restrict__ B, float* __restrict__ C,
    float* __restrict__ Aw, float* __restrict__ rs,
    int K, int lda, int ldb, int ldc,
    long long sA, long long sB, long long sC, float alpha, int S)
{
    extern __shared__ char smem[];
    const uint32_t sbase = smem_u32(smem);
    const int tid = threadIdx.x;
    const int lane = tid & 31;
    const int warp = tid >> 5;
    const int lg = lane >> 2;          // 0..7
    const int l4 = lane & 3;           // 0..3
    const int wm = (warp & 3) * 64;
    const int wn = (warp >> 2) * 64;

    const int m0 = blockIdx.y * MT;
    const int n0 = blockIdx.x * NT;

    const float* Ab = A + (long long)blockIdx.z * sA + (long long)m0 * lda;
    float* Awb = NORM ? (Aw + (long long)blockIdx.z * sA + (long long)m0 * lda) : nullptr;
    const float* Bb;
    if (TB) Bb = B + (long long)blockIdx.z * sB + (long long)n0 * ldb;
    else    Bb = B + (long long)blockIdx.z * sB + n0;
    float* Cb = C + (long long)blockIdx.z * sC + (long long)m0 * ldc + n0;

    // loader mappings
    const int a_r = tid >> 3;            // 0..31 (+32i), rows (A and TB-B)
    const int a_c = (tid & 7) * 4;       // float col base (16B chunk)
    const int bn_k = tid >> 5;           // 0..7 (+8i)
    const int bn_c = (tid & 31) * 4;

    float inv[8];
    if (NORM) {
#pragma unroll
        for (int i = 0; i < 8; i++)
            inv[i] = rs[blockIdx.z * S + m0 + a_r + 32 * i];
    }

    float acc[4][8][4];
#pragma unroll
    for (int mt = 0; mt < 4; mt++)
#pragma unroll
        for (int nt = 0; nt < 8; nt++)
#pragma unroll
            for (int i = 0; i < 4; i++) acc[mt][nt][i] = 0.0f;

    const int ktiles = K / BK;
    float4 pa[8];   // only used when NORM

    auto issueA = [&](int st, int kt) {
        const uint32_t as = sbase + st * STAGE_BYTES;
        const float* p = Ab + (long long)a_r * lda + kt * BK + a_c;
#pragma unroll
        for (int i = 0; i < 8; i++)
            cp16(as + (uint32_t)(((a_r + 32 * i) * AS_STRIDE + a_c) * 4),
                 p + (long long)(32 * i) * lda);
    };
    auto issueB = [&](int st, int kt) {
        const uint32_t bs = sbase + st * STAGE_BYTES + A_BYTES;
        if (TB) {
            const float* p = Bb + (long long)a_r * ldb + kt * BK + a_c;
#pragma unroll
            for (int i = 0; i < 4; i++)
                cp16(bs + (uint32_t)(((a_r + 32 * i) * AS_STRIDE + a_c) * 4),
                     p + (long long)(32 * i) * ldb);
        } else {
            const float* p = Bb + (long long)(kt * BK + bn_k) * ldb + bn_c;
#pragma unroll
            for (int i = 0; i < 4; i++)
                cp16(bs + (uint32_t)(((bn_k + 8 * i) * BS_STRIDE + bn_c) * 4),
                     p + (long long)(8 * i) * ldb);
        }
    };
    auto ldAreg = [&](int kt) {
        const float* p = Ab + (long long)a_r * lda + kt * BK + a_c;
#pragma unroll
        for (int i = 0; i < 8; i++)
            pa[i] = *(const float4*)(p + (long long)(32 * i) * lda);
    };
    // NORM: write e*inv to gmem (final attn), stage RAW e into smem
    auto stAnorm = [&](int st, int kt) {
        float* As = (float*)(smem + st * STAGE_BYTES);
#pragma unroll
        for (int i = 0; i < 8; i++) {
            float4 v = pa[i];
            float4 w;
            w.x = v.x * inv[i]; w.y = v.y * inv[i];
            w.z = v.z * inv[i]; w.w = v.w * inv[i];
            *(float4*)(Awb + (long long)(a_r + 32 * i) * lda + kt * BK + a_c) = w;
            *(float4*)&As[(a_r + 32 * i) * AS_STRIDE + a_c] = v;
        }
    };

    // ---- prologue: fill stages 0..2 ----
#pragma unroll
    for (int s = 0; s < 3; s++) {
        if (!NORM) issueA(s, s);
        issueB(s, s);
        CP_COMMIT();
        if (NORM) { ldAreg(s); stAnorm(s, s); }
    }

    for (int kt = 0; kt < ktiles; kt++) {
        const int cur = kt % STAGES;
        if (kt + 2 < ktiles)      CP_WAIT2();
        else if (kt + 1 < ktiles) CP_WAIT1();
        else                      CP_WAIT0();
        __syncthreads();

        const int nx = (kt + 3) % STAGES;
        const bool has = (kt + 3 < ktiles);
        if (has) {
            if (!NORM) issueA(nx, kt + 3);
            issueB(nx, kt + 3);
            CP_COMMIT();
            if (NORM) ldAreg(kt + 3);
        }

        const float* As = (const float*)(smem + cur * STAGE_BYTES);
        const float* Bs = (const float*)(smem + cur * STAGE_BYTES + A_BYTES);
#pragma unroll
        for (int ks = 0; ks < 4; ks++) {
            const int k = ks * 8;
            unsigned a[4][4], b[8][2];
#pragma unroll
            for (int mt = 0; mt < 4; mt++) {
                const int r = wm + mt * 16 + lg;
                unsigned v0 = __float_as_uint(As[r * AS_STRIDE + k + l4]);
                unsigned v1 = __float_as_uint(As[(r + 8) * AS_STRIDE + k + l4]);
                unsigned v2 = __float_as_uint(As[r * AS_STRIDE + k + l4 + 4]);
                unsigned v3 = __float_as_uint(As[(r + 8) * AS_STRIDE + k + l4 + 4]);
                a[mt][0] = CVA ? tf32u(v0) : v0;
                a[mt][1] = CVA ? tf32u(v1) : v1;
                a[mt][2] = CVA ? tf32u(v2) : v2;
                a[mt][3] = CVA ? tf32u(v3) : v3;
            }
#pragma unroll
            for (int nt = 0; nt < 8; nt++) {
                const int c = wn + nt * 8 + lg;
                unsigned v0, v1;
                if (TB) {
                    v0 = __float_as_uint(Bs[c * AS_STRIDE + k + l4]);
                    v1 = __float_as_uint(Bs[c * AS_STRIDE + k + l4 + 4]);
                } else {
                    v0 = __float_as_uint(Bs[(k + l4) * BS_STRIDE + c]);
                    v1 = __float_as_uint(Bs[(k + l4 + 4) * BS_STRIDE + c]);
                }
                b[nt][0] = CVB ? tf32u(v0) : v0;
                b[nt][1] = CVB ? tf32u(v1) : v1;
            }
#pragma unroll
            for (int mt = 0; mt < 4; mt++)
#pragma unroll
                for (int nt = 0; nt < 8; nt++)
                    mma_tf32(acc[mt][nt], a[mt], b[nt]);
        }

        if (has && NORM) stAnorm(nx, kt + 3);
    }

    // ---- epilogue ----
    if (EXPE) {
        float ps[4][2];
#pragma unroll
        for (int mt = 0; mt < 4; mt++) { ps[mt][0] = 0.0f; ps[mt][1] = 0.0f; }
#pragma unroll
        for (int mt = 0; mt < 4; mt++) {
            const int r = wm + mt * 16 + lg;
#pragma unroll
            for (int nt = 0; nt < 8; nt++) {
                const int c = wn + nt * 8 + 2 * l4;
                float e0 = tf32f(__expf(acc[mt][nt][0] * alpha));
                float e1 = tf32f(__expf(acc[mt][nt][1] * alpha));
                float e2 = tf32f(__expf(acc[mt][nt][2] * alpha));
                float e3 = tf32f(__expf(acc[mt][nt][3] * alpha));
                *(float2*)(Cb + (long long)r * ldc + c) = make_float2(e0, e1);
                *(float2*)(Cb + (long long)(r + 8) * ldc + c) = make_float2(e2, e3);
                ps[mt][0] += e0 + e1;
                ps[mt][1] += e2 + e3;
            }
        }
#pragma unroll
        for (int mt = 0; mt < 4; mt++) {
#pragma unroll
            for (int h = 0; h < 2; h++) {
                float v = ps[mt][h];
                v += __shfl_xor_sync(0xffffffffu, v, 1);
                v += __shfl_xor_sync(0xffffffffu, v, 2);
                if (l4 == 0)
                    atomicAdd(&rs[blockIdx.z * S + m0 + wm + mt * 16 + lg + h * 8], v);
            }
        }
    } else {
#pragma unroll
        for (int mt = 0; mt < 4; mt++) {
            const int r = wm + mt * 16 + lg;
            float s0 = alpha, s1 = alpha;
            if (NORM) {
                s0 = rs[blockIdx.z * S + m0 + r];
                s1 = rs[blockIdx.z * S + m0 + r + 8];
            }
#pragma unroll
            for (int nt = 0; nt < 8; nt++) {
                const int c = wn + nt * 8 + 2 * l4;
                float o0 = acc[mt][nt][0] * s0, o1 = acc[mt][nt][1] * s0;
                float o2 = acc[mt][nt][2] * s1, o3 = acc[mt][nt][3] * s1;
                if (ROUND) {
                    o0 = tf32f(o0); o1 = tf32f(o1);
                    o2 = tf32f(o2); o3 = tf32f(o3);
                }
                *(float2*)(Cb + (long long)r * ldc + c) = make_float2(o0, o1);
                *(float2*)(Cb + (long long)(r + 8) * ldc + c) = make_float2(o2, o3);
            }
        }
    }
}

__global__ void zero_rs(float* rs, int n) {
    int i = blockIdx.x * blockDim.x + threadIdx.x;
    if (i < n) rs[i] = 0.0f;
}
__global__ void inv_rs(float* rs, int n) {
    int i = blockIdx.x * blockDim.x + threadIdx.x;
    if (i < n) rs[i] = 1.0f / rs[i];
}

extern "C" void kernel_launch(void* const* d_in, const int* in_sizes, int n_in,
                              void* d_out, int out_size)
{
    const float* x  = (const float*)d_in[0];
    const float* Wq = (const float*)d_in[1];
    const float* Wk = (const float*)d_in[2];
    const float* Wv = (const float*)d_in[3];
    const float* Wo = (const float*)d_in[4];

    const int F  = 1024;
    const int H  = 1024;
    const int NH = NHEAD;
    const int DK = H / NH;                 // 128
    const int S  = in_sizes[0] / F;        // 4096

    float* y_out    = (float*)d_out;
    float* attn_out = y_out + (long long)S * H;

    float *q, *k, *v, *y, *rs;
    cudaGetSymbolAddress((void**)&q, g_q);
    cudaGetSymbolAddress((void**)&k, g_k);
    cudaGetSymbolAddress((void**)&v, g_v);
    cudaGetSymbolAddress((void**)&y, g_y);
    cudaGetSymbolAddress((void**)&rs, g_rs);

    // template args: TB, EXPE, NORM, CVA, CVB, ROUND
    auto kQKV  = gemm_mha<false, false, false, true,  true,  true >;
    auto kQKT  = gemm_mha<true,  true,  false, false, false, false>;
    auto kAV   = gemm_mha<false, false, true,  false, false, true >;
    auto kPROJ = gemm_mha<false, false, false, false, true,  false>;

    cudaFuncSetAttribute(kQKV,  cudaFuncAttributeMaxDynamicSharedMemorySize, SMEM_DYN);
    cudaFuncSetAttribute(kQKT,  cudaFuncAttributeMaxDynamicSharedMemorySize, SMEM_DYN);
    cudaFuncSetAttribute(kAV,   cudaFuncAttributeMaxDynamicSharedMemorySize, SMEM_DYN);
    cudaFuncSetAttribute(kPROJ, cudaFuncAttributeMaxDynamicSharedMemorySize, SMEM_DYN);

    const dim3 blk(256);
    const float inv_sqrt_dk = 0.08838834764831845f;  // 1/sqrt(128)

    // 0) zero row sums (graph-replay safe)
    zero_rs<<<(NH * S + 255) / 256, 256>>>(rs, NH * S);

    // 1) Q/K/V projections: [S,F] @ [F,H], outputs tf32-rounded
    dim3 g1(H / NT, S / MT, 1);
    kQKV<<<g1, blk, SMEM_DYN>>>(x, Wq, q, nullptr, rs, F, F, H, H, 0, 0, 0, 1.0f, S);
    kQKV<<<g1, blk, SMEM_DYN>>>(x, Wk, k, nullptr, rs, F, F, H, H, 0, 0, 0, 1.0f, S);
    kQKV<<<g1, blk, SMEM_DYN>>>(x, Wv, v, nullptr, rs, F, F, H, H, 0, 0, 0, 1.0f, S);

    // 2) logits -> tf32(exp(Q K^T / sqrt(dk))) into attn region + row sums
    dim3 g2(S / NT, S / MT, NH);
    kQKT<<<g2, blk, SMEM_DYN>>>(q, k, attn_out, nullptr, rs, DK, H, H, S,
                                (long long)DK, (long long)DK, (long long)S * S,
                                inv_sqrt_dk, S);

    // 3) invert row sums
    inv_rs<<<(NH * S + 255) / 256, 256>>>(rs, NH * S);

    // 4) AV: Y = inv.(E @ V); loader writes normalized attn back; Y rounded
    dim3 g3(DK / NT, S / MT, NH);
    kAV<<<g3, blk, SMEM_DYN>>>(attn_out, v, y, attn_out, rs, S, S, H, H,
                               (long long)S * S, (long long)DK, (long long)DK,
                               1.0f, S);

    // 5) output projection: y_out = Y @ Wo (fp32 out)
    dim3 g4(F / NT, S / MT, 1);
    kPROJ<<<g4, blk, SMEM_DYN>>>(y, Wo, y_out, nullptr, rs, H, H, F, F,
                                 0, 0, 0, 1.0f, S);
}

// round 8
// speedup vs baseline: 1.1555x; 1.0455x over previous
#include <cuda_runtime.h>
#include <cstdint>
#include <math.h>

// ---------------------------------------------------------------------------
// MultiHeadAttention, tf32 mma.sync GEMMs, cp.async 3-stage pipelines,
// fused softmax. CTA 128x128x32, 4 warps (2x2 of 64x64 warp tiles),
// 2 CTAs/SM so exp-epilogues overlap mainloops across CTAs.
// d_out = y [S,F] then attn [8,S,S] (fp32). S=4096, F=H=1024, dk=128.
// ---------------------------------------------------------------------------

#define SMAX 4096
#define HMAX 1024
#define NHEAD 8

__device__ float g_q[SMAX * HMAX];
__device__ float g_k[SMAX * HMAX];
__device__ float g_v[SMAX * HMAX];
__device__ float g_y[SMAX * HMAX];
__device__ float g_rs[NHEAD * SMAX];   // row sums of exp -> inverted in place

__device__ __forceinline__ unsigned tf32u(unsigned x) {
    unsigned r;
    asm("cvt.rna.tf32.f32 %0, %1;" : "=r"(r) : "f"(__uint_as_float(x)));
    return r;
}
__device__ __forceinline__ float tf32f(float x) {
    unsigned r;
    asm("cvt.rna.tf32.f32 %0, %1;" : "=r"(r) : "f"(x));
    return __uint_as_float(r);
}
__device__ __forceinline__ void mma_tf32(float* c, const unsigned* a, const unsigned* b) {
    asm volatile(
        "mma.sync.aligned.m16n8k8.row.col.f32.tf32.tf32.f32 "
        "{%0,%1,%2,%3}, {%4,%5,%6,%7}, {%8,%9}, {%0,%1,%2,%3};"
        : "+f"(c[0]), "+f"(c[1]), "+f"(c[2]), "+f"(c[3])
        : "r"(a[0]), "r"(a[1]), "r"(a[2]), "r"(a[3]), "r"(b[0]), "r"(b[1]));
}
__device__ __forceinline__ uint32_t smem_u32(const void* p) {
    uint32_t a;
    asm("{ .reg .u64 t; cvta.to.shared.u64 t, %1; cvt.u32.u64 %0, t; }" : "=r"(a) : "l"(p));
    return a;
}
__device__ __forceinline__ void cp16(uint32_t s, const void* g) {
    asm volatile("cp.async.cg.shared.global [%0], [%1], 16;" :: "r"(s), "l"(g));
}
#define CP_COMMIT() asm volatile("cp.async.commit_group;")
#define CP_WAIT1()  asm volatile("cp.async.wait_group 1;")
#define CP_WAIT0()  asm volatile("cp.async.wait_group 0;")

// Tile config: CTA 128(M) x 128(N) x 32(K), 4 warps (2m x 2n), warp tile 64x64.
#define MT  128
#define NT  128
#define BK  32
#define STAGES 3
#define NTHREADS 128
#define AS_STRIDE 36      // floats; [m][k] and TB [n][k]
#define BS_STRIDE 136     // NN layout [k][n]
#define A_BYTES  (128 * AS_STRIDE * 4)           // 18432
#define B_BYTES  (128 * AS_STRIDE * 4)           // 18432 (covers NN 17408 too)
#define STAGE_BYTES (A_BYTES + B_BYTES)          // 36864
#define SMEM_DYN (STAGES * STAGE_BYTES)          // 110592  (x2 CTAs = 221184)

// ---------------------------------------------------------------------------
// TB=false: C = alpha * A[M,K] @ B[K,N]   (B row-major; Bs [k][n] stride 136)
// TB=true : C = alpha * A[M,K] @ B[N,K]^T (B K-major;   Bs [n][k] stride 36)
// EXPE : epilogue C = exp(alpha*acc) fp32, atomicAdd fp32 row sums into rs
// NORM : A via LDG; e*inv written back to Aw (final normalized attn, fp32);
//        tf32(e) staged to smem; epilogue scales acc rows by inv (rs).
// CVA/CVB : cvt.rna.tf32 on A/B fragments (external fp32 operands only)
// ROUND : round plain epilogue output to tf32 (when C feeds another GEMM)
// ---------------------------------------------------------------------------
template <bool TB, bool EXPE, bool NORM, bool CVA, bool CVB, bool ROUND>
__global__ void __launch_bounds__(NTHREADS, 2) gemm_mha(
    const float* __restrict__ A, const float* __restrict__ B, float* __restrict__ C,
    float* __restrict__ Aw, float* __restrict__ rs,
    int K, int lda, int ldb, int ldc,
    long long sA, long long sB, long long sC, float alpha, int S)
{
    extern __shared__ char smem[];
    const uint32_t sbase = smem_u32(smem);
    const int tid = threadIdx.x;
    const int lane = tid & 31;
    const int warp = tid >> 5;
    const int lg = lane >> 2;          // 0..7
    const int l4 = lane & 3;           // 0..3
    const int wm = (warp & 1) * 64;    // 2 m-warps
    const int wn = (warp >> 1) * 64;   // 2 n-warps

    const int m0 = blockIdx.y * MT;
    const int n0 = blockIdx.x * NT;

    const float* Ab = A + (long long)blockIdx.z * sA + (long long)m0 * lda;
    float* Awb = NORM ? (Aw + (long long)blockIdx.z * sA + (long long)m0 * lda) : nullptr;
    const float* Bb;
    if (TB) Bb = B + (long long)blockIdx.z * sB + (long long)n0 * ldb;
    else    Bb = B + (long long)blockIdx.z * sB + n0;
    float* Cb = C + (long long)blockIdx.z * sC + (long long)m0 * ldc + n0;

    // loader mappings (128 threads)
    const int a_r = tid >> 3;            // 0..15 (+16i, i=0..7)
    const int a_c = (tid & 7) * 4;       // float col base (16B chunk)
    const int bn_k = tid >> 5;           // 0..3 (+4i, i=0..7)
    const int bn_c = (tid & 31) * 4;

    float inv[8];
    if (NORM) {
#pragma unroll
        for (int i = 0; i < 8; i++)
            inv[i] = rs[blockIdx.z * S + m0 + a_r + 16 * i];
    }

    float acc[4][8][4];
#pragma unroll
    for (int mt = 0; mt < 4; mt++)
#pragma unroll
        for (int nt = 0; nt < 8; nt++)
#pragma unroll
            for (int i = 0; i < 4; i++) acc[mt][nt][i] = 0.0f;

    const int ktiles = K / BK;
    float4 pa[8];   // only used when NORM

    auto issueA = [&](int st, int kt) {
        const uint32_t as = sbase + st * STAGE_BYTES;
        const float* p = Ab + (long long)a_r * lda + kt * BK + a_c;
#pragma unroll
        for (int i = 0; i < 8; i++)
            cp16(as + (uint32_t)(((a_r + 16 * i) * AS_STRIDE + a_c) * 4),
                 p + (long long)(16 * i) * lda);
    };
    auto issueB = [&](int st, int kt) {
        const uint32_t bs = sbase + st * STAGE_BYTES + A_BYTES;
        if (TB) {
            const float* p = Bb + (long long)a_r * ldb + kt * BK + a_c;
#pragma unroll
            for (int i = 0; i < 8; i++)
                cp16(bs + (uint32_t)(((a_r + 16 * i) * AS_STRIDE + a_c) * 4),
                     p + (long long)(16 * i) * ldb);
        } else {
            const float* p = Bb + (long long)(kt * BK + bn_k) * ldb + bn_c;
#pragma unroll
            for (int i = 0; i < 8; i++)
                cp16(bs + (uint32_t)(((bn_k + 4 * i) * BS_STRIDE + bn_c) * 4),
                     p + (long long)(4 * i) * ldb);
        }
    };
    auto ldAreg = [&](int kt) {
        const float* p = Ab + (long long)a_r * lda + kt * BK + a_c;
#pragma unroll
        for (int i = 0; i < 8; i++)
            pa[i] = *(const float4*)(p + (long long)(16 * i) * lda);
    };
    // NORM: write e*inv to gmem (final attn), stage tf32(e) into smem
    auto stAnorm = [&](int st, int kt) {
        float* As = (float*)(smem + st * STAGE_BYTES);
#pragma unroll
        for (int i = 0; i < 8; i++) {
            float4 v = pa[i];
            float4 w;
            w.x = v.x * inv[i]; w.y = v.y * inv[i];
            w.z = v.z * inv[i]; w.w = v.w * inv[i];
            *(float4*)(Awb + (long long)(a_r + 16 * i) * lda + kt * BK + a_c) = w;
            float4 t;
            t.x = tf32f(v.x); t.y = tf32f(v.y); t.z = tf32f(v.z); t.w = tf32f(v.w);
            *(float4*)&As[(a_r + 16 * i) * AS_STRIDE + a_c] = t;
        }
    };

    // ---- prologue: fill stages 0,1 ----
#pragma unroll
    for (int s = 0; s < 2; s++) {
        if (!NORM) issueA(s, s);
        issueB(s, s);
        CP_COMMIT();
        if (NORM) { ldAreg(s); stAnorm(s, s); }
    }

    for (int kt = 0; kt < ktiles; kt++) {
        const int cur = kt % STAGES;
        const bool has = (kt + 2 < ktiles);
        if (has) CP_WAIT1(); else CP_WAIT0();
        __syncthreads();

        const int nx = (kt + 2) % STAGES;
        if (has) {
            if (!NORM) issueA(nx, kt + 2);
            issueB(nx, kt + 2);
            CP_COMMIT();
            if (NORM) ldAreg(kt + 2);
        }

        const float* As = (const float*)(smem + cur * STAGE_BYTES);
        const float* Bs = (const float*)(smem + cur * STAGE_BYTES + A_BYTES);
#pragma unroll
        for (int ks = 0; ks < 4; ks++) {
            const int k = ks * 8;
            unsigned a[4][4], b[8][2];
#pragma unroll
            for (int mt = 0; mt < 4; mt++) {
                const int r = wm + mt * 16 + lg;
                unsigned v0 = __float_as_uint(As[r * AS_STRIDE + k + l4]);
                unsigned v1 = __float_as_uint(As[(r + 8) * AS_STRIDE + k + l4]);
                unsigned v2 = __float_as_uint(As[r * AS_STRIDE + k + l4 + 4]);
                unsigned v3 = __float_as_uint(As[(r + 8) * AS_STRIDE + k + l4 + 4]);
                a[mt][0] = CVA ? tf32u(v0) : v0;
                a[mt][1] = CVA ? tf32u(v1) : v1;
                a[mt][2] = CVA ? tf32u(v2) : v2;
                a[mt][3] = CVA ? tf32u(v3) : v3;
            }
#pragma unroll
            for (int nt = 0; nt < 8; nt++) {
                const int c = wn + nt * 8 + lg;
                unsigned v0, v1;
                if (TB) {
                    v0 = __float_as_uint(Bs[c * AS_STRIDE + k + l4]);
                    v1 = __float_as_uint(Bs[c * AS_STRIDE + k + l4 + 4]);
                } else {
                    v0 = __float_as_uint(Bs[(k + l4) * BS_STRIDE + c]);
                    v1 = __float_as_uint(Bs[(k + l4 + 4) * BS_STRIDE + c]);
                }
                b[nt][0] = CVB ? tf32u(v0) : v0;
                b[nt][1] = CVB ? tf32u(v1) : v1;
            }
#pragma unroll
            for (int mt = 0; mt < 4; mt++)
#pragma unroll
                for (int nt = 0; nt < 8; nt++)
                    mma_tf32(acc[mt][nt], a[mt], b[nt]);
        }

        if (has && NORM) stAnorm(nx, kt + 2);
    }

    // ---- epilogue ----
    if (EXPE) {
        float ps[4][2];
#pragma unroll
        for (int mt = 0; mt < 4; mt++) { ps[mt][0] = 0.0f; ps[mt][1] = 0.0f; }
#pragma unroll
        for (int mt = 0; mt < 4; mt++) {
            const int r = wm + mt * 16 + lg;
#pragma unroll
            for (int nt = 0; nt < 8; nt++) {
                const int c = wn + nt * 8 + 2 * l4;
                float e0 = __expf(acc[mt][nt][0] * alpha);
                float e1 = __expf(acc[mt][nt][1] * alpha);
                float e2 = __expf(acc[mt][nt][2] * alpha);
                float e3 = __expf(acc[mt][nt][3] * alpha);
                *(float2*)(Cb + (long long)r * ldc + c) = make_float2(e0, e1);
                *(float2*)(Cb + (long long)(r + 8) * ldc + c) = make_float2(e2, e3);
                ps[mt][0] += e0 + e1;
                ps[mt][1] += e2 + e3;
            }
        }
#pragma unroll
        for (int mt = 0; mt < 4; mt++) {
#pragma unroll
            for (int h = 0; h < 2; h++) {
                float v = ps[mt][h];
                v += __shfl_xor_sync(0xffffffffu, v, 1);
                v += __shfl_xor_sync(0xffffffffu, v, 2);
                if (l4 == 0)
                    atomicAdd(&rs[blockIdx.z * S + m0 + wm + mt * 16 + lg + h * 8], v);
            }
        }
    } else {
#pragma unroll
        for (int mt = 0; mt < 4; mt++) {
            const int r = wm + mt * 16 + lg;
            float s0 = alpha, s1 = alpha;
            if (NORM) {
                s0 = rs[blockIdx.z * S + m0 + r];
                s1 = rs[blockIdx.z * S + m0 + r + 8];
            }
#pragma unroll
            for (int nt = 0; nt < 8; nt++) {
                const int c = wn + nt * 8 + 2 * l4;
                float o0 = acc[mt][nt][0] * s0, o1 = acc[mt][nt][1] * s0;
                float o2 = acc[mt][nt][2] * s1, o3 = acc[mt][nt][3] * s1;
                if (ROUND) {
                    o0 = tf32f(o0); o1 = tf32f(o1);
                    o2 = tf32f(o2); o3 = tf32f(o3);
                }
                *(float2*)(Cb + (long long)r * ldc + c) = make_float2(o0, o1);
                *(float2*)(Cb + (long long)(r + 8) * ldc + c) = make_float2(o2, o3);
            }
        }
    }
}

__global__ void zero_rs(float* rs, int n) {
    int i = blockIdx.x * blockDim.x + threadIdx.x;
    if (i < n) rs[i] = 0.0f;
}
__global__ void inv_rs(float* rs, int n) {
    int i = blockIdx.x * blockDim.x + threadIdx.x;
    if (i < n) rs[i] = 1.0f / rs[i];
}

extern "C" void kernel_launch(void* const* d_in, const int* in_sizes, int n_in,
                              void* d_out, int out_size)
{
    const float* x  = (const float*)d_in[0];
    const float* Wq = (const float*)d_in[1];
    const float* Wk = (const float*)d_in[2];
    const float* Wv = (const float*)d_in[3];
    const float* Wo = (const float*)d_in[4];

    const int F  = 1024;
    const int H  = 1024;
    const int NH = NHEAD;
    const int DK = H / NH;                 // 128
    const int S  = in_sizes[0] / F;        // 4096

    float* y_out    = (float*)d_out;
    float* attn_out = y_out + (long long)S * H;

    float *q, *k, *v, *y, *rs;
    cudaGetSymbolAddress((void**)&q, g_q);
    cudaGetSymbolAddress((void**)&k, g_k);
    cudaGetSymbolAddress((void**)&v, g_v);
    cudaGetSymbolAddress((void**)&y, g_y);
    cudaGetSymbolAddress((void**)&rs, g_rs);

    // template args: TB, EXPE, NORM, CVA, CVB, ROUND
    auto kQKV  = gemm_mha<false, false, false, true,  true,  true >;
    auto kQKT  = gemm_mha<true,  true,  false, false, false, false>;
    auto kAV   = gemm_mha<false, false, true,  false, false, true >;
    auto kPROJ = gemm_mha<false, false, false, false, true,  false>;

    cudaFuncSetAttribute(kQKV,  cudaFuncAttributeMaxDynamicSharedMemorySize, SMEM_DYN);
    cudaFuncSetAttribute(kQKT,  cudaFuncAttributeMaxDynamicSharedMemorySize, SMEM_DYN);
    cudaFuncSetAttribute(kAV,   cudaFuncAttributeMaxDynamicSharedMemorySize, SMEM_DYN);
    cudaFuncSetAttribute(kPROJ, cudaFuncAttributeMaxDynamicSharedMemorySize, SMEM_DYN);

    const dim3 blk(NTHREADS);
    const float inv_sqrt_dk = 0.08838834764831845f;  // 1/sqrt(128)

    // 0) zero row sums (graph-replay safe)
    zero_rs<<<(NH * S + 255) / 256, 256>>>(rs, NH * S);

    // 1) Q/K/V projections: [S,F] @ [F,H], outputs tf32-rounded
    dim3 g1(H / NT, S / MT, 1);
    kQKV<<<g1, blk, SMEM_DYN>>>(x, Wq, q, nullptr, rs, F, F, H, H, 0, 0, 0, 1.0f, S);
    kQKV<<<g1, blk, SMEM_DYN>>>(x, Wk, k, nullptr, rs, F, F, H, H, 0, 0, 0, 1.0f, S);
    kQKV<<<g1, blk, SMEM_DYN>>>(x, Wv, v, nullptr, rs, F, F, H, H, 0, 0, 0, 1.0f, S);

    // 2) logits -> exp(Q K^T / sqrt(dk)) fp32 into attn region + row sums
    dim3 g2(S / NT, S / MT, NH);
    kQKT<<<g2, blk, SMEM_DYN>>>(q, k, attn_out, nullptr, rs, DK, H, H, S,
                                (long long)DK, (long long)DK, (long long)S * S,
                                inv_sqrt_dk, S);

    // 3) invert row sums
    inv_rs<<<(NH * S + 255) / 256, 256>>>(rs, NH * S);

    // 4) AV: Y = inv.(E @ V); loader writes normalized attn back; Y rounded
    dim3 g3(DK / NT, S / MT, NH);
    kAV<<<g3, blk, SMEM_DYN>>>(attn_out, v, y, attn_out, rs, S, S, H, H,
                               (long long)S * S, (long long)DK, (long long)DK,
                               1.0f, S);

    // 5) output projection: y_out = Y @ Wo (fp32 out)
    dim3 g4(F / NT, S / MT, 1);
    kPROJ<<<g4, blk, SMEM_DYN>>>(y, Wo, y_out, nullptr, rs, H, H, F, F,
                                 0, 0, 0, 1.0f, S);
}

// round 9
// speedup vs baseline: 1.1767x; 1.0183x over previous
#include <cuda_runtime.h>
#include <cstdint>
#include <math.h>

// ---------------------------------------------------------------------------
// MultiHeadAttention, tf32 mma.sync GEMMs, cp.async 3-stage pipelines,
// fragment double-buffering, fused softmax, fused QKV (one launch).
// CTA 128x128x32, 4 warps (2x2 of 64x64 warp tiles), 2 CTAs/SM.
// d_out = y [S,F] then attn [8,S,S] (fp32). S=4096, F=H=1024, dk=128.
// ---------------------------------------------------------------------------

#define SMAX 4096
#define HMAX 1024
#define NHEAD 8

__device__ float g_qkv[3 * SMAX * HMAX];     // q | k | v contiguous
__device__ float g_y[SMAX * HMAX];
__device__ float g_rs[NHEAD * SMAX];         // row sums of exp -> inverted

__device__ __forceinline__ unsigned tf32u(unsigned x) {
    unsigned r;
    asm("cvt.rna.tf32.f32 %0, %1;" : "=r"(r) : "f"(__uint_as_float(x)));
    return r;
}
__device__ __forceinline__ float tf32f(float x) {
    unsigned r;
    asm("cvt.rna.tf32.f32 %0, %1;" : "=r"(r) : "f"(x));
    return __uint_as_float(r);
}
__device__ __forceinline__ void mma_tf32(float* c, const unsigned* a, const unsigned* b) {
    asm volatile(
        "mma.sync.aligned.m16n8k8.row.col.f32.tf32.tf32.f32 "
        "{%0,%1,%2,%3}, {%4,%5,%6,%7}, {%8,%9}, {%0,%1,%2,%3};"
        : "+f"(c[0]), "+f"(c[1]), "+f"(c[2]), "+f"(c[3])
        : "r"(a[0]), "r"(a[1]), "r"(a[2]), "r"(a[3]), "r"(b[0]), "r"(b[1]));
}
__device__ __forceinline__ uint32_t smem_u32(const void* p) {
    uint32_t a;
    asm("{ .reg .u64 t; cvta.to.shared.u64 t, %1; cvt.u32.u64 %0, t; }" : "=r"(a) : "l"(p));
    return a;
}
__device__ __forceinline__ void cp16(uint32_t s, const void* g) {
    asm volatile("cp.async.cg.shared.global [%0], [%1], 16;" :: "r"(s), "l"(g));
}
#define CP_COMMIT() asm volatile("cp.async.commit_group;")
#define CP_WAIT1()  asm volatile("cp.async.wait_group 1;")
#define CP_WAIT0()  asm volatile("cp.async.wait_group 0;")

// Tile config: CTA 128(M) x 128(N) x 32(K), 4 warps (2m x 2n), warp tile 64x64.
#define MT  128
#define NT  128
#define BK  32
#define STAGES 3
#define NTHREADS 128
#define AS_STRIDE 36      // floats; [m][k] and TB [n][k]
#define BS_STRIDE 136     // NN layout [k][n]
#define A_BYTES  (128 * AS_STRIDE * 4)           // 18432
#define B_BYTES  (128 * AS_STRIDE * 4)           // 18432 (covers NN 17408 too)
#define STAGE_BYTES (A_BYTES + B_BYTES)          // 36864
#define SMEM_DYN (STAGES * STAGE_BYTES)          // 110592  (x2 CTAs = 221184)

// ---------------------------------------------------------------------------
// TB=false: C = alpha * A[M,K] @ B[K,N]   (B row-major; Bs [k][n] stride 136)
// TB=true : C = alpha * A[M,K] @ B[N,K]^T (B K-major;   Bs [n][k] stride 36)
// EXPE : epilogue C = exp(alpha*acc) fp32, atomicAdd fp32 row sums into rs
// NORM : A via LDG; e*inv written back to Aw (final normalized attn, fp32);
//        tf32(e) staged to smem; epilogue scales acc rows by inv (rs).
// CVA/CVB : cvt.rna.tf32 on A/B fragments (external fp32 operands only)
// ROUND : round plain epilogue output to tf32 (when C feeds another GEMM)
// QKV3 : blockIdx.x encodes (matrix sel << 3) | n-tile; B in {B0,B1,B2},
//        C += sel * sC. (requires N = 1024 -> 8 n-tiles)
// ---------------------------------------------------------------------------
template <bool TB, bool EXPE, bool NORM, bool CVA, bool CVB, bool ROUND, bool QKV3>
__global__ void __launch_bounds__(NTHREADS, 2) gemm_mha(
    const float* __restrict__ A, const float* __restrict__ B0,
    const float* __restrict__ B1, const float* __restrict__ B2,
    float* __restrict__ C, float* __restrict__ Aw, float* __restrict__ rs,
    int K, int lda, int ldb, int ldc,
    long long sA, long long sB, long long sC, float alpha, int S)
{
    extern __shared__ char smem[];
    const uint32_t sbase = smem_u32(smem);
    const int tid = threadIdx.x;
    const int lane = tid & 31;
    const int warp = tid >> 5;
    const int lg = lane >> 2;          // 0..7
    const int l4 = lane & 3;           // 0..3
    const int wm = (warp & 1) * 64;    // 2 m-warps
    const int wn = (warp >> 1) * 64;   // 2 n-warps

    const int m0 = blockIdx.y * MT;
    int n0;
    const float* B;
    float* Cm;
    if (QKV3) {
        const int bsel = blockIdx.x >> 3;
        n0 = (blockIdx.x & 7) * NT;
        B = (bsel == 0) ? B0 : ((bsel == 1) ? B1 : B2);
        Cm = C + (long long)bsel * sC;
    } else {
        n0 = blockIdx.x * NT;
        B = B0;
        Cm = C + (long long)blockIdx.z * sC;
    }

    const float* Ab = A + (long long)blockIdx.z * sA + (long long)m0 * lda;
    float* Awb = NORM ? (Aw + (long long)blockIdx.z * sA + (long long)m0 * lda) : nullptr;
    const float* Bb;
    if (TB) Bb = B + (long long)blockIdx.z * sB + (long long)n0 * ldb;
    else    Bb = B + (long long)blockIdx.z * sB + n0;
    float* Cb = Cm + (long long)m0 * ldc + n0;

    // loader mappings (128 threads)
    const int a_r = tid >> 3;            // 0..15 (+16i, i=0..7)
    const int a_c = (tid & 7) * 4;       // float col base (16B chunk)
    const int bn_k = tid >> 5;           // 0..3 (+4i, i=0..7)
    const int bn_c = (tid & 31) * 4;

    float inv[8];
    if (NORM) {
#pragma unroll
        for (int i = 0; i < 8; i++)
            inv[i] = rs[blockIdx.z * S + m0 + a_r + 16 * i];
    }

    float acc[4][8][4];
#pragma unroll
    for (int mt = 0; mt < 4; mt++)
#pragma unroll
        for (int nt = 0; nt < 8; nt++)
#pragma unroll
            for (int i = 0; i < 4; i++) acc[mt][nt][i] = 0.0f;

    const int ktiles = K / BK;
    float4 pa[8];   // only used when NORM

    auto issueA = [&](int st, int kt) {
        const uint32_t as = sbase + st * STAGE_BYTES;
        const float* p = Ab + (long long)a_r * lda + kt * BK + a_c;
#pragma unroll
        for (int i = 0; i < 8; i++)
            cp16(as + (uint32_t)(((a_r + 16 * i) * AS_STRIDE + a_c) * 4),
                 p + (long long)(16 * i) * lda);
    };
    auto issueB = [&](int st, int kt) {
        const uint32_t bs = sbase + st * STAGE_BYTES + A_BYTES;
        if (TB) {
            const float* p = Bb + (long long)a_r * ldb + kt * BK + a_c;
#pragma unroll
            for (int i = 0; i < 8; i++)
                cp16(bs + (uint32_t)(((a_r + 16 * i) * AS_STRIDE + a_c) * 4),
                     p + (long long)(16 * i) * ldb);
        } else {
            const float* p = Bb + (long long)(kt * BK + bn_k) * ldb + bn_c;
#pragma unroll
            for (int i = 0; i < 8; i++)
                cp16(bs + (uint32_t)(((bn_k + 4 * i) * BS_STRIDE + bn_c) * 4),
                     p + (long long)(4 * i) * ldb);
        }
    };
    auto ldAreg = [&](int kt) {
        const float* p = Ab + (long long)a_r * lda + kt * BK + a_c;
#pragma unroll
        for (int i = 0; i < 8; i++)
            pa[i] = *(const float4*)(p + (long long)(16 * i) * lda);
    };
    // NORM: write e*inv to gmem (final attn), stage tf32(e) into smem
    auto stAnorm = [&](int st, int kt) {
        float* As = (float*)(smem + st * STAGE_BYTES);
#pragma unroll
        for (int i = 0; i < 8; i++) {
            float4 v = pa[i];
            float4 w;
            w.x = v.x * inv[i]; w.y = v.y * inv[i];
            w.z = v.z * inv[i]; w.w = v.w * inv[i];
            *(float4*)(Awb + (long long)(a_r + 16 * i) * lda + kt * BK + a_c) = w;
            float4 t;
            t.x = tf32f(v.x); t.y = tf32f(v.y); t.z = tf32f(v.z); t.w = tf32f(v.w);
            *(float4*)&As[(a_r + 16 * i) * AS_STRIDE + a_c] = t;
        }
    };

    // ---- prologue: fill stages 0,1 ----
#pragma unroll
    for (int s = 0; s < 2; s++) {
        if (!NORM) issueA(s, s);
        issueB(s, s);
        CP_COMMIT();
        if (NORM) { ldAreg(s); stAnorm(s, s); }
    }

    for (int kt = 0; kt < ktiles; kt++) {
        const int cur = kt % STAGES;
        const bool has = (kt + 2 < ktiles);
        if (has) CP_WAIT1(); else CP_WAIT0();
        __syncthreads();

        const int nx = (kt + 2) % STAGES;
        if (has) {
            if (!NORM) issueA(nx, kt + 2);
            issueB(nx, kt + 2);
            CP_COMMIT();
            if (NORM) ldAreg(kt + 2);
        }

        const float* As = (const float*)(smem + cur * STAGE_BYTES);
        const float* Bs = (const float*)(smem + cur * STAGE_BYTES + A_BYTES);

        // fragment double-buffer across the 4 ks steps
        unsigned af[2][4][4], bf[2][8][2];
        auto ldfrag = [&](int ks, int buf) {
            const int k = ks * 8;
#pragma unroll
            for (int mt = 0; mt < 4; mt++) {
                const int r = wm + mt * 16 + lg;
                unsigned v0 = __float_as_uint(As[r * AS_STRIDE + k + l4]);
                unsigned v1 = __float_as_uint(As[(r + 8) * AS_STRIDE + k + l4]);
                unsigned v2 = __float_as_uint(As[r * AS_STRIDE + k + l4 + 4]);
                unsigned v3 = __float_as_uint(As[(r + 8) * AS_STRIDE + k + l4 + 4]);
                af[buf][mt][0] = CVA ? tf32u(v0) : v0;
                af[buf][mt][1] = CVA ? tf32u(v1) : v1;
                af[buf][mt][2] = CVA ? tf32u(v2) : v2;
                af[buf][mt][3] = CVA ? tf32u(v3) : v3;
            }
#pragma unroll
            for (int nt = 0; nt < 8; nt++) {
                const int c = wn + nt * 8 + lg;
                unsigned v0, v1;
                if (TB) {
                    v0 = __float_as_uint(Bs[c * AS_STRIDE + k + l4]);
                    v1 = __float_as_uint(Bs[c * AS_STRIDE + k + l4 + 4]);
                } else {
                    v0 = __float_as_uint(Bs[(k + l4) * BS_STRIDE + c]);
                    v1 = __float_as_uint(Bs[(k + l4 + 4) * BS_STRIDE + c]);
                }
                bf[buf][nt][0] = CVB ? tf32u(v0) : v0;
                bf[buf][nt][1] = CVB ? tf32u(v1) : v1;
            }
        };

        ldfrag(0, 0);
#pragma unroll
        for (int ks = 0; ks < 4; ks++) {
            const int cb = ks & 1;
            if (ks < 3) ldfrag(ks + 1, cb ^ 1);
#pragma unroll
            for (int mt = 0; mt < 4; mt++)
#pragma unroll
                for (int nt = 0; nt < 8; nt++)
                    mma_tf32(acc[mt][nt], af[cb][mt], bf[cb][nt]);
        }

        if (has && NORM) stAnorm(nx, kt + 2);
    }

    // ---- epilogue ----
    if (EXPE) {
        float ps[4][2];
#pragma unroll
        for (int mt = 0; mt < 4; mt++) { ps[mt][0] = 0.0f; ps[mt][1] = 0.0f; }
#pragma unroll
        for (int mt = 0; mt < 4; mt++) {
            const int r = wm + mt * 16 + lg;
#pragma unroll
            for (int nt = 0; nt < 8; nt++) {
                const int c = wn + nt * 8 + 2 * l4;
                float e0 = __expf(acc[mt][nt][0] * alpha);
                float e1 = __expf(acc[mt][nt][1] * alpha);
                float e2 = __expf(acc[mt][nt][2] * alpha);
                float e3 = __expf(acc[mt][nt][3] * alpha);
                *(float2*)(Cb + (long long)r * ldc + c) = make_float2(e0, e1);
                *(float2*)(Cb + (long long)(r + 8) * ldc + c) = make_float2(e2, e3);
                ps[mt][0] += e0 + e1;
                ps[mt][1] += e2 + e3;
            }
        }
#pragma unroll
        for (int mt = 0; mt < 4; mt++) {
#pragma unroll
            for (int h = 0; h < 2; h++) {
                float v = ps[mt][h];
                v += __shfl_xor_sync(0xffffffffu, v, 1);
                v += __shfl_xor_sync(0xffffffffu, v, 2);
                if (l4 == 0)
                    atomicAdd(&rs[blockIdx.z * S + m0 + wm + mt * 16 + lg + h * 8], v);
            }
        }
    } else {
#pragma unroll
        for (int mt = 0; mt < 4; mt++) {
            const int r = wm + mt * 16 + lg;
            float s0 = alpha, s1 = alpha;
            if (NORM) {
                s0 = rs[blockIdx.z * S + m0 + r];
                s1 = rs[blockIdx.z * S + m0 + r + 8];
            }
#pragma unroll
            for (int nt = 0; nt < 8; nt++) {
                const int c = wn + nt * 8 + 2 * l4;
                float o0 = acc[mt][nt][0] * s0, o1 = acc[mt][nt][1] * s0;
                float o2 = acc[mt][nt][2] * s1, o3 = acc[mt][nt][3] * s1;
                if (ROUND) {
                    o0 = tf32f(o0); o1 = tf32f(o1);
                    o2 = tf32f(o2); o3 = tf32f(o3);
                }
                *(float2*)(Cb + (long long)r * ldc + c) = make_float2(o0, o1);
                *(float2*)(Cb + (long long)(r + 8) * ldc + c) = make_float2(o2, o3);
            }
        }
    }
}

__global__ void zero_rs(float* rs, int n) {
    int i = blockIdx.x * blockDim.x + threadIdx.x;
    if (i < n) rs[i] = 0.0f;
}
__global__ void inv_rs(float* rs, int n) {
    int i = blockIdx.x * blockDim.x + threadIdx.x;
    if (i < n) rs[i] = 1.0f / rs[i];
}

extern "C" void kernel_launch(void* const* d_in, const int* in_sizes, int n_in,
                              void* d_out, int out_size)
{
    const float* x  = (const float*)d_in[0];
    const float* Wq = (const float*)d_in[1];
    const float* Wk = (const float*)d_in[2];
    const float* Wv = (const float*)d_in[3];
    const float* Wo = (const float*)d_in[4];

    const int F  = 1024;
    const int H  = 1024;
    const int NH = NHEAD;
    const int DK = H / NH;                 // 128
    const int S  = in_sizes[0] / F;        // 4096

    float* y_out    = (float*)d_out;
    float* attn_out = y_out + (long long)S * H;

    float *qkv, *y, *rs;
    cudaGetSymbolAddress((void**)&qkv, g_qkv);
    cudaGetSymbolAddress((void**)&y, g_y);
    cudaGetSymbolAddress((void**)&rs, g_rs);
    float* q = qkv;
    float* k = qkv + (long long)S * H;
    float* v = qkv + 2LL * S * H;

    // template args: TB, EXPE, NORM, CVA, CVB, ROUND, QKV3
    auto kQKV  = gemm_mha<false, false, false, true,  true,  true,  true >;
    auto kQKT  = gemm_mha<true,  true,  false, false, false, false, false>;
    auto kAV   = gemm_mha<false, false, true,  false, false, true,  false>;
    auto kPROJ = gemm_mha<false, false, false, false, true,  false, false>;

    cudaFuncSetAttribute(kQKV,  cudaFuncAttributeMaxDynamicSharedMemorySize, SMEM_DYN);
    cudaFuncSetAttribute(kQKT,  cudaFuncAttributeMaxDynamicSharedMemorySize, SMEM_DYN);
    cudaFuncSetAttribute(kAV,   cudaFuncAttributeMaxDynamicSharedMemorySize, SMEM_DYN);
    cudaFuncSetAttribute(kPROJ, cudaFuncAttributeMaxDynamicSharedMemorySize, SMEM_DYN);

    const dim3 blk(NTHREADS);
    const float inv_sqrt_dk = 0.08838834764831845f;  // 1/sqrt(128)

    // 0) zero row sums (graph-replay safe)
    zero_rs<<<(NH * S + 255) / 256, 256>>>(rs, NH * S);

    // 1) fused Q/K/V projections: one launch, 3 * (H/NT) n-tiles in x
    dim3 g1(3 * (H / NT), S / MT, 1);
    kQKV<<<g1, blk, SMEM_DYN>>>(x, Wq, Wk, Wv, qkv, nullptr, rs,
                                F, F, H, H, 0, 0, (long long)S * H, 1.0f, S);

    // 2) logits -> exp(Q K^T / sqrt(dk)) fp32 into attn region + row sums
    dim3 g2(S / NT, S / MT, NH);
    kQKT<<<g2, blk, SMEM_DYN>>>(q, k, nullptr, nullptr, attn_out, nullptr, rs,
                                DK, H, H, S,
                                (long long)DK, (long long)DK, (long long)S * S,
                                inv_sqrt_dk, S);

    // 3) invert row sums
    inv_rs<<<(NH * S + 255) / 256, 256>>>(rs, NH * S);

    // 4) AV: Y = inv.(E @ V); loader writes normalized attn back; Y rounded
    dim3 g3(DK / NT, S / MT, NH);
    kAV<<<g3, blk, SMEM_DYN>>>(attn_out, v, nullptr, nullptr, y, attn_out, rs,
                               S, S, H, H,
                               (long long)S * S, (long long)DK, (long long)DK,
                               1.0f, S);

    // 5) output projection: y_out = Y @ Wo (fp32 out)
    dim3 g4(F / NT, S / MT, 1);
    kPROJ<<<g4, blk, SMEM_DYN>>>(y, Wo, nullptr, nullptr, y_out, nullptr, rs,
                                 H, H, F, F, 0, 0, 0, 1.0f, S);
}

// round 10
// speedup vs baseline: 1.1937x; 1.0144x over previous
#include <cuda_runtime.h>
#include <cstdint>
#include <math.h>

// ---------------------------------------------------------------------------
// MultiHeadAttention, tf32 mma.sync GEMMs, cp.async 3-stage pipelines,
// ldmatrix fragment loads, fragment double-buffering, fused softmax,
// fused QKV. CTA 128x128x32, 4 warps (2x2 of 64x64 warp tiles), 2 CTAs/SM.
// d_out = y [S,F] then attn [8,S,S] (fp32). S=4096, F=H=1024, dk=128.
// ---------------------------------------------------------------------------

#define SMAX 4096
#define HMAX 1024
#define NHEAD 8

__device__ float g_qkv[3 * SMAX * HMAX];     // q | k | v contiguous
__device__ float g_y[SMAX * HMAX];
__device__ float g_rs[NHEAD * SMAX];         // row sums of exp -> inverted

__device__ __forceinline__ unsigned tf32u(unsigned x) {
    unsigned r;
    asm("cvt.rna.tf32.f32 %0, %1;" : "=r"(r) : "f"(__uint_as_float(x)));
    return r;
}
__device__ __forceinline__ float tf32f(float x) {
    unsigned r;
    asm("cvt.rna.tf32.f32 %0, %1;" : "=r"(r) : "f"(x));
    return __uint_as_float(r);
}
__device__ __forceinline__ void mma_tf32(float* c, const unsigned* a, const unsigned* b) {
    asm volatile(
        "mma.sync.aligned.m16n8k8.row.col.f32.tf32.tf32.f32 "
        "{%0,%1,%2,%3}, {%4,%5,%6,%7}, {%8,%9}, {%0,%1,%2,%3};"
        : "+f"(c[0]), "+f"(c[1]), "+f"(c[2]), "+f"(c[3])
        : "r"(a[0]), "r"(a[1]), "r"(a[2]), "r"(a[3]), "r"(b[0]), "r"(b[1]));
}
__device__ __forceinline__ void ldsm4(unsigned* r, uint32_t a) {
    asm volatile("ldmatrix.sync.aligned.m8n8.x4.shared.b16 {%0,%1,%2,%3}, [%4];"
        : "=r"(r[0]), "=r"(r[1]), "=r"(r[2]), "=r"(r[3]) : "r"(a));
}
__device__ __forceinline__ uint32_t smem_u32(const void* p) {
    uint32_t a;
    asm("{ .reg .u64 t; cvta.to.shared.u64 t, %1; cvt.u32.u64 %0, t; }" : "=r"(a) : "l"(p));
    return a;
}
__device__ __forceinline__ void cp16(uint32_t s, const void* g) {
    asm volatile("cp.async.cg.shared.global [%0], [%1], 16;" :: "r"(s), "l"(g));
}
#define CP_COMMIT() asm volatile("cp.async.commit_group;")
#define CP_WAIT1()  asm volatile("cp.async.wait_group 1;")
#define CP_WAIT0()  asm volatile("cp.async.wait_group 0;")

// Tile config: CTA 128(M) x 128(N) x 32(K), 4 warps (2m x 2n), warp tile 64x64.
#define MT  128
#define NT  128
#define BK  32
#define STAGES 3
#define NTHREADS 128
#define AS_STRIDE 36      // floats; [m][k] and TB [n][k]
#define BS_STRIDE 136     // NN layout [k][n]
#define A_BYTES  (128 * AS_STRIDE * 4)           // 18432
#define B_BYTES  (128 * AS_STRIDE * 4)           // 18432 (covers NN 17408 too)
#define STAGE_BYTES (A_BYTES + B_BYTES)          // 36864
#define SMEM_DYN (STAGES * STAGE_BYTES)          // 110592  (x2 CTAs = 221184)

// ---------------------------------------------------------------------------
// TB=false: C = alpha * A[M,K] @ B[K,N]   (B row-major; Bs [k][n] stride 136)
// TB=true : C = alpha * A[M,K] @ B[N,K]^T (B K-major;   Bs [n][k] stride 36)
// EXPE : epilogue C = exp(alpha*acc) fp32, atomicAdd fp32 row sums into rs
// NORM : A via LDG; e*inv written back to Aw (final normalized attn, fp32);
//        tf32(e) staged to smem; epilogue scales acc rows by inv (rs).
// CVA/CVB : cvt.rna.tf32 on A/B fragments (external fp32 operands only)
// ROUND : round plain epilogue output to tf32 (when C feeds another GEMM)
// QKV3 : blockIdx.x encodes (matrix sel << 3) | n-tile
// ---------------------------------------------------------------------------
template <bool TB, bool EXPE, bool NORM, bool CVA, bool CVB, bool ROUND, bool QKV3>
__global__ void __launch_bounds__(NTHREADS, 2) gemm_mha(
    const float* __restrict__ A, const float* __restrict__ B0,
    const float* __restrict__ B1, const float* __restrict__ B2,
    float* __restrict__ C, float* __restrict__ Aw, float* __restrict__ rs,
    int K, int lda, int ldb, int ldc,
    long long sA, long long sB, long long sC, float alpha, int S)
{
    extern __shared__ char smem[];
    const uint32_t sbase = smem_u32(smem);
    const int tid = threadIdx.x;
    const int lane = tid & 31;
    const int warp = tid >> 5;
    const int lg = lane >> 2;          // 0..7
    const int l4 = lane & 3;           // 0..3
    const int wm = (warp & 1) * 64;    // 2 m-warps
    const int wn = (warp >> 1) * 64;   // 2 n-warps

    // ldmatrix lane offsets (bytes, relative to tile base)
    const int lgp = lane >> 3, ri = lane & 7;
    const uint32_t aoff = (uint32_t)((wm + ((lgp & 1) << 3) + ri) * (AS_STRIDE * 4)
                                     + ((lgp >> 1) << 4));
    const uint32_t boff = (uint32_t)((wn + ((lgp >> 1) << 3) + ri) * (AS_STRIDE * 4)
                                     + ((lgp & 1) << 4));   // TB layout only

    const int m0 = blockIdx.y * MT;
    int n0;
    const float* B;
    float* Cm;
    if (QKV3) {
        const int bsel = blockIdx.x >> 3;
        n0 = (blockIdx.x & 7) * NT;
        B = (bsel == 0) ? B0 : ((bsel == 1) ? B1 : B2);
        Cm = C + (long long)bsel * sC;
    } else {
        n0 = blockIdx.x * NT;
        B = B0;
        Cm = C + (long long)blockIdx.z * sC;
    }

    const float* Ab = A + (long long)blockIdx.z * sA + (long long)m0 * lda;
    float* Awb = NORM ? (Aw + (long long)blockIdx.z * sA + (long long)m0 * lda) : nullptr;
    const float* Bb;
    if (TB) Bb = B + (long long)blockIdx.z * sB + (long long)n0 * ldb;
    else    Bb = B + (long long)blockIdx.z * sB + n0;
    float* Cb = Cm + (long long)m0 * ldc + n0;

    // loader mappings (128 threads)
    const int a_r = tid >> 3;            // 0..15 (+16i, i=0..7)
    const int a_c = (tid & 7) * 4;       // float col base (16B chunk)
    const int bn_k = tid >> 5;           // 0..3 (+4i, i=0..7)
    const int bn_c = (tid & 31) * 4;

    float inv[8];
    if (NORM) {
#pragma unroll
        for (int i = 0; i < 8; i++)
            inv[i] = rs[blockIdx.z * S + m0 + a_r + 16 * i];
    }

    float acc[4][8][4];
#pragma unroll
    for (int mt = 0; mt < 4; mt++)
#pragma unroll
        for (int nt = 0; nt < 8; nt++)
#pragma unroll
            for (int i = 0; i < 4; i++) acc[mt][nt][i] = 0.0f;

    const int ktiles = K / BK;
    float4 pa[8];   // only used when NORM

    auto issueA = [&](int st, int kt) {
        const uint32_t as = sbase + st * STAGE_BYTES;
        const float* p = Ab + (long long)a_r * lda + kt * BK + a_c;
#pragma unroll
        for (int i = 0; i < 8; i++)
            cp16(as + (uint32_t)(((a_r + 16 * i) * AS_STRIDE + a_c) * 4),
                 p + (long long)(16 * i) * lda);
    };
    auto issueB = [&](int st, int kt) {
        const uint32_t bs = sbase + st * STAGE_BYTES + A_BYTES;
        if (TB) {
            const float* p = Bb + (long long)a_r * ldb + kt * BK + a_c;
#pragma unroll
            for (int i = 0; i < 8; i++)
                cp16(bs + (uint32_t)(((a_r + 16 * i) * AS_STRIDE + a_c) * 4),
                     p + (long long)(16 * i) * ldb);
        } else {
            const float* p = Bb + (long long)(kt * BK + bn_k) * ldb + bn_c;
#pragma unroll
            for (int i = 0; i < 8; i++)
                cp16(bs + (uint32_t)(((bn_k + 4 * i) * BS_STRIDE + bn_c) * 4),
                     p + (long long)(4 * i) * ldb);
        }
    };
    auto ldAreg = [&](int kt) {
        const float* p = Ab + (long long)a_r * lda + kt * BK + a_c;
#pragma unroll
        for (int i = 0; i < 8; i++)
            pa[i] = *(const float4*)(p + (long long)(16 * i) * lda);
    };
    // NORM: write e*inv to gmem (final attn), stage tf32(e) into smem
    auto stAnorm = [&](int st, int kt) {
        float* As = (float*)(smem + st * STAGE_BYTES);
#pragma unroll
        for (int i = 0; i < 8; i++) {
            float4 v = pa[i];
            float4 w;
            w.x = v.x * inv[i]; w.y = v.y * inv[i];
            w.z = v.z * inv[i]; w.w = v.w * inv[i];
            *(float4*)(Awb + (long long)(a_r + 16 * i) * lda + kt * BK + a_c) = w;
            float4 t;
            t.x = tf32f(v.x); t.y = tf32f(v.y); t.z = tf32f(v.z); t.w = tf32f(v.w);
            *(float4*)&As[(a_r + 16 * i) * AS_STRIDE + a_c] = t;
        }
    };

    // ---- prologue: fill stages 0,1 ----
#pragma unroll
    for (int s = 0; s < 2; s++) {
        if (!NORM) issueA(s, s);
        issueB(s, s);
        CP_COMMIT();
        if (NORM) { ldAreg(s); stAnorm(s, s); }
    }

    for (int kt = 0; kt < ktiles; kt++) {
        const int cur = kt % STAGES;
        const bool has = (kt + 2 < ktiles);
        if (has) CP_WAIT1(); else CP_WAIT0();
        __syncthreads();

        const int nx = (kt + 2) % STAGES;
        if (has) {
            if (!NORM) issueA(nx, kt + 2);
            issueB(nx, kt + 2);
            CP_COMMIT();
            if (NORM) ldAreg(kt + 2);
        }

        const uint32_t as_s = sbase + cur * STAGE_BYTES;
        const uint32_t bs_s = as_s + A_BYTES;
        const float* Bs = (const float*)(smem + cur * STAGE_BYTES + A_BYTES);

        // fragment double-buffer across the 4 ks steps
        unsigned af[2][4][4], bf[2][8][2];
        auto ldfrag = [&](int ks, int buf) {
            const int k = ks * 8;
            // A fragments: one ldmatrix.x4 per mt
#pragma unroll
            for (int mt = 0; mt < 4; mt++) {
                unsigned r[4];
                ldsm4(r, as_s + aoff + (uint32_t)(mt * 16 * AS_STRIDE * 4 + ks * 32));
                af[buf][mt][0] = CVA ? tf32u(r[0]) : r[0];
                af[buf][mt][1] = CVA ? tf32u(r[1]) : r[1];
                af[buf][mt][2] = CVA ? tf32u(r[2]) : r[2];
                af[buf][mt][3] = CVA ? tf32u(r[3]) : r[3];
            }
            if (TB) {
                // B fragments: one ldmatrix.x4 per nt-pair
#pragma unroll
                for (int np = 0; np < 4; np++) {
                    unsigned r[4];
                    ldsm4(r, bs_s + boff + (uint32_t)(np * 16 * AS_STRIDE * 4 + ks * 32));
                    bf[buf][2 * np][0]     = CVB ? tf32u(r[0]) : r[0];
                    bf[buf][2 * np][1]     = CVB ? tf32u(r[1]) : r[1];
                    bf[buf][2 * np + 1][0] = CVB ? tf32u(r[2]) : r[2];
                    bf[buf][2 * np + 1][1] = CVB ? tf32u(r[3]) : r[3];
                }
            } else {
#pragma unroll
                for (int nt = 0; nt < 8; nt++) {
                    const int c = wn + nt * 8 + lg;
                    unsigned v0 = __float_as_uint(Bs[(k + l4) * BS_STRIDE + c]);
                    unsigned v1 = __float_as_uint(Bs[(k + l4 + 4) * BS_STRIDE + c]);
                    bf[buf][nt][0] = CVB ? tf32u(v0) : v0;
                    bf[buf][nt][1] = CVB ? tf32u(v1) : v1;
                }
            }
        };

        ldfrag(0, 0);
#pragma unroll
        for (int ks = 0; ks < 4; ks++) {
            const int cb = ks & 1;
            if (ks < 3) ldfrag(ks + 1, cb ^ 1);
#pragma unroll
            for (int mt = 0; mt < 4; mt++)
#pragma unroll
                for (int nt = 0; nt < 8; nt++)
                    mma_tf32(acc[mt][nt], af[cb][mt], bf[cb][nt]);
        }

        if (has && NORM) stAnorm(nx, kt + 2);
    }

    // ---- epilogue ----
    if (EXPE) {
        float ps[4][2];
#pragma unroll
        for (int mt = 0; mt < 4; mt++) { ps[mt][0] = 0.0f; ps[mt][1] = 0.0f; }
#pragma unroll
        for (int mt = 0; mt < 4; mt++) {
            const int r = wm + mt * 16 + lg;
#pragma unroll
            for (int nt = 0; nt < 8; nt++) {
                const int c = wn + nt * 8 + 2 * l4;
                float e0 = __expf(acc[mt][nt][0] * alpha);
                float e1 = __expf(acc[mt][nt][1] * alpha);
                float e2 = __expf(acc[mt][nt][2] * alpha);
                float e3 = __expf(acc[mt][nt][3] * alpha);
                *(float2*)(Cb + (long long)r * ldc + c) = make_float2(e0, e1);
                *(float2*)(Cb + (long long)(r + 8) * ldc + c) = make_float2(e2, e3);
                ps[mt][0] += e0 + e1;
                ps[mt][1] += e2 + e3;
            }
        }
#pragma unroll
        for (int mt = 0; mt < 4; mt++) {
#pragma unroll
            for (int h = 0; h < 2; h++) {
                float v = ps[mt][h];
                v += __shfl_xor_sync(0xffffffffu, v, 1);
                v += __shfl_xor_sync(0xffffffffu, v, 2);
                if (l4 == 0)
                    atomicAdd(&rs[blockIdx.z * S + m0 + wm + mt * 16 + lg + h * 8], v);
            }
        }
    } else {
#pragma unroll
        for (int mt = 0; mt < 4; mt++) {
            const int r = wm + mt * 16 + lg;
            float s0 = alpha, s1 = alpha;
            if (NORM) {
                s0 = rs[blockIdx.z * S + m0 + r];
                s1 = rs[blockIdx.z * S + m0 + r + 8];
            }
#pragma unroll
            for (int nt = 0; nt < 8; nt++) {
                const int c = wn + nt * 8 + 2 * l4;
                float o0 = acc[mt][nt][0] * s0, o1 = acc[mt][nt][1] * s0;
                float o2 = acc[mt][nt][2] * s1, o3 = acc[mt][nt][3] * s1;
                if (ROUND) {
                    o0 = tf32f(o0); o1 = tf32f(o1);
                    o2 = tf32f(o2); o3 = tf32f(o3);
                }
                *(float2*)(Cb + (long long)r * ldc + c) = make_float2(o0, o1);
                *(float2*)(Cb + (long long)(r + 8) * ldc + c) = make_float2(o2, o3);
            }
        }
    }
}

__global__ void zero_rs(float* rs, int n) {
    int i = blockIdx.x * blockDim.x + threadIdx.x;
    if (i < n) rs[i] = 0.0f;
}
__global__ void inv_rs(float* rs, int n) {
    int i = blockIdx.x * blockDim.x + threadIdx.x;
    if (i < n) rs[i] = 1.0f / rs[i];
}

extern "C" void kernel_launch(void* const* d_in, const int* in_sizes, int n_in,
                              void* d_out, int out_size)
{
    const float* x  = (const float*)d_in[0];
    const float* Wq = (const float*)d_in[1];
    const float* Wk = (const float*)d_in[2];
    const float* Wv = (const float*)d_in[3];
    const float* Wo = (const float*)d_in[4];

    const int F  = 1024;
    const int H  = 1024;
    const int NH = NHEAD;
    const int DK = H / NH;                 // 128
    const int S  = in_sizes[0] / F;        // 4096

    float* y_out    = (float*)d_out;
    float* attn_out = y_out + (long long)S * H;

    float *qkv, *y, *rs;
    cudaGetSymbolAddress((void**)&qkv, g_qkv);
    cudaGetSymbolAddress((void**)&y, g_y);
    cudaGetSymbolAddress((void**)&rs, g_rs);
    float* q = qkv;
    float* k = qkv + (long long)S * H;
    float* v = qkv + 2LL * S * H;

    // template args: TB, EXPE, NORM, CVA, CVB, ROUND, QKV3
    auto kQKV  = gemm_mha<false, false, false, true,  true,  true,  true >;
    auto kQKT  = gemm_mha<true,  true,  false, false, false, false, false>;
    auto kAV   = gemm_mha<false, false, true,  false, false, true,  false>;
    auto kPROJ = gemm_mha<false, false, false, false, true,  false, false>;

    cudaFuncSetAttribute(kQKV,  cudaFuncAttributeMaxDynamicSharedMemorySize, SMEM_DYN);
    cudaFuncSetAttribute(kQKT,  cudaFuncAttributeMaxDynamicSharedMemorySize, SMEM_DYN);
    cudaFuncSetAttribute(kAV,   cudaFuncAttributeMaxDynamicSharedMemorySize, SMEM_DYN);
    cudaFuncSetAttribute(kPROJ, cudaFuncAttributeMaxDynamicSharedMemorySize, SMEM_DYN);

    const dim3 blk(NTHREADS);
    const float inv_sqrt_dk = 0.08838834764831845f;  // 1/sqrt(128)

    // 0) zero row sums (graph-replay safe)
    zero_rs<<<(NH * S + 255) / 256, 256>>>(rs, NH * S);

    // 1) fused Q/K/V projections: one launch, 3 * (H/NT) n-tiles in x
    dim3 g1(3 * (H / NT), S / MT, 1);
    kQKV<<<g1, blk, SMEM_DYN>>>(x, Wq, Wk, Wv, qkv, nullptr, rs,
                                F, F, H, H, 0, 0, (long long)S * H, 1.0f, S);

    // 2) logits -> exp(Q K^T / sqrt(dk)) fp32 into attn region + row sums
    dim3 g2(S / NT, S / MT, NH);
    kQKT<<<g2, blk, SMEM_DYN>>>(q, k, nullptr, nullptr, attn_out, nullptr, rs,
                                DK, H, H, S,
                                (long long)DK, (long long)DK, (long long)S * S,
                                inv_sqrt_dk, S);

    // 3) invert row sums
    inv_rs<<<(NH * S + 255) / 256, 256>>>(rs, NH * S);

    // 4) AV: Y = inv.(E @ V); loader writes normalized attn back; Y rounded
    dim3 g3(DK / NT, S / MT, NH);
    kAV<<<g3, blk, SMEM_DYN>>>(attn_out, v, nullptr, nullptr, y, attn_out, rs,
                               S, S, H, H,
                               (long long)S * S, (long long)DK, (long long)DK,
                               1.0f, S);

    // 5) output projection: y_out = Y @ Wo (fp32 out)
    dim3 g4(F / NT, S / MT, 1);
    kPROJ<<<g4, blk, SMEM_DYN>>>(y, Wo, nullptr, nullptr, y_out, nullptr, rs,
                                 H, H, F, F, 0, 0, 0, 1.0f, S);
}

// round 11
// speedup vs baseline: 1.1995x; 1.0049x over previous
#include <cuda_runtime.h>
#include <cstdint>
#include <math.h>

// ---------------------------------------------------------------------------
// MultiHeadAttention, tf32 mma.sync GEMMs, cp.async 3-stage pipelines,
// ldmatrix fragment loads, fragment double-buffering, fused softmax,
// fused QKV (v written transposed so AV is an all-ldsm TB GEMM).
// CTA 128x128x32, 4 warps (2x2 of 64x64 warp tiles), 2 CTAs/SM.
// d_out = y [S,F] then attn [8,S,S] (fp32). S=4096, F=H=1024, dk=128.
// ---------------------------------------------------------------------------

#define SMAX 4096
#define HMAX 1024
#define NHEAD 8

__device__ float g_qkv[3 * SMAX * HMAX];     // q | k | (v unused plane)
__device__ float g_vt[HMAX * SMAX];          // v transposed [H][S]
__device__ float g_y[SMAX * HMAX];
__device__ float g_rs[NHEAD * SMAX];         // row sums of exp -> inverted

__device__ __forceinline__ unsigned tf32u(unsigned x) {
    unsigned r;
    asm("cvt.rna.tf32.f32 %0, %1;" : "=r"(r) : "f"(__uint_as_float(x)));
    return r;
}
__device__ __forceinline__ float tf32f(float x) {
    unsigned r;
    asm("cvt.rna.tf32.f32 %0, %1;" : "=r"(r) : "f"(x));
    return __uint_as_float(r);
}
__device__ __forceinline__ void mma_tf32(float* c, const unsigned* a, const unsigned* b) {
    asm volatile(
        "mma.sync.aligned.m16n8k8.row.col.f32.tf32.tf32.f32 "
        "{%0,%1,%2,%3}, {%4,%5,%6,%7}, {%8,%9}, {%0,%1,%2,%3};"
        : "+f"(c[0]), "+f"(c[1]), "+f"(c[2]), "+f"(c[3])
        : "r"(a[0]), "r"(a[1]), "r"(a[2]), "r"(a[3]), "r"(b[0]), "r"(b[1]));
}
__device__ __forceinline__ void ldsm4(unsigned* r, uint32_t a) {
    asm volatile("ldmatrix.sync.aligned.m8n8.x4.shared.b16 {%0,%1,%2,%3}, [%4];"
        : "=r"(r[0]), "=r"(r[1]), "=r"(r[2]), "=r"(r[3]) : "r"(a));
}
__device__ __forceinline__ uint32_t smem_u32(const void* p) {
    uint32_t a;
    asm("{ .reg .u64 t; cvta.to.shared.u64 t, %1; cvt.u32.u64 %0, t; }" : "=r"(a) : "l"(p));
    return a;
}
__device__ __forceinline__ void cp16(uint32_t s, const void* g) {
    asm volatile("cp.async.cg.shared.global [%0], [%1], 16;" :: "r"(s), "l"(g));
}
#define CP_COMMIT() asm volatile("cp.async.commit_group;")
#define CP_WAIT1()  asm volatile("cp.async.wait_group 1;")
#define CP_WAIT0()  asm volatile("cp.async.wait_group 0;")

// Tile config: CTA 128(M) x 128(N) x 32(K), 4 warps (2m x 2n), warp tile 64x64.
#define MT  128
#define NT  128
#define BK  32
#define STAGES 3
#define NTHREADS 128
#define AS_STRIDE 36      // floats; [m][k] and TB [n][k]
#define BS_STRIDE 136     // NN layout [k][n]
#define A_BYTES  (128 * AS_STRIDE * 4)           // 18432
#define B_BYTES  (128 * AS_STRIDE * 4)           // 18432 (covers NN 17408 too)
#define STAGE_BYTES (A_BYTES + B_BYTES)          // 36864
#define SMEM_DYN (STAGES * STAGE_BYTES)          // 110592  (x2 CTAs = 221184)

// ---------------------------------------------------------------------------
// TB=false: C = alpha * A[M,K] @ B[K,N]   (B row-major; Bs [k][n] stride 136)
// TB=true : C = alpha * A[M,K] @ B[N,K]^T (B K-major;   Bs [n][k] stride 36)
// EXPE : epilogue C = exp(alpha*acc) fp32, atomicAdd fp32 row sums into rs
// NORM : A via LDG; e*inv written back to Aw (final normalized attn, fp32);
//        tf32(e) staged to smem; epilogue scales acc rows by inv (rs).
// CVA/CVB : cvt.rna.tf32 on A/B fragments (external fp32 operands only)
// ROUND : round plain epilogue output to tf32 (when C feeds another GEMM)
// QKV3 : blockIdx.x = (bsel << 3) | n-tile; bsel 2 (v) stores transposed
//        into Aw as [H][S]; also CTAs with blockIdx.x==0 zero rs.
// ---------------------------------------------------------------------------
template <bool TB, bool EXPE, bool NORM, bool CVA, bool CVB, bool ROUND, bool QKV3>
__global__ void __launch_bounds__(NTHREADS, 2) gemm_mha(
    const float* __restrict__ A, const float* __restrict__ B0,
    const float* __restrict__ B1, const float* __restrict__ B2,
    float* __restrict__ C, float* __restrict__ Aw, float* __restrict__ rs,
    int K, int lda, int ldb, int ldc,
    long long sA, long long sB, long long sC, float alpha, int S)
{
    extern __shared__ char smem[];
    const uint32_t sbase = smem_u32(smem);
    const int tid = threadIdx.x;
    const int lane = tid & 31;
    const int warp = tid >> 5;
    const int lg = lane >> 2;          // 0..7
    const int l4 = lane & 3;           // 0..3
    const int wm = (warp & 1) * 64;    // 2 m-warps
    const int wn = (warp >> 1) * 64;   // 2 n-warps

    // ldmatrix lane offsets (bytes, relative to tile base)
    const int lgp = lane >> 3, ri = lane & 7;
    const uint32_t aoff = (uint32_t)((wm + ((lgp & 1) << 3) + ri) * (AS_STRIDE * 4)
                                     + ((lgp >> 1) << 4));
    const uint32_t boff = (uint32_t)((wn + ((lgp >> 1) << 3) + ri) * (AS_STRIDE * 4)
                                     + ((lgp & 1) << 4));   // TB layout only

    const int m0 = blockIdx.y * MT;
    int n0;
    const float* B;
    float* Cm;
    bool trc = false;
    if (QKV3) {
        const int bsel = blockIdx.x >> 3;
        n0 = (blockIdx.x & 7) * NT;
        B = (bsel == 0) ? B0 : ((bsel == 1) ? B1 : B2);
        Cm = C + (long long)bsel * sC;
        trc = (bsel == 2);
        // fused rs zeroing (32 CTAs with blockIdx.x==0 cover NHEAD*S floats)
        if (blockIdx.x == 0) {
            float4 z = make_float4(0.f, 0.f, 0.f, 0.f);
            float* p = rs + blockIdx.y * (NHEAD * S / 32) + tid * 8;
            *(float4*)p = z;
            *(float4*)(p + 4) = z;
        }
    } else {
        n0 = blockIdx.x * NT;
        B = B0;
        Cm = C + (long long)blockIdx.z * sC;
    }

    const float* Ab = A + (long long)blockIdx.z * sA + (long long)m0 * lda;
    float* Awb = NORM ? (Aw + (long long)blockIdx.z * sA + (long long)m0 * lda) : nullptr;
    const float* Bb;
    if (TB) Bb = B + (long long)blockIdx.z * sB + (long long)n0 * ldb;
    else    Bb = B + (long long)blockIdx.z * sB + n0;
    float* Cb = Cm + (long long)m0 * ldc + n0;

    // loader mappings (128 threads)
    const int a_r = tid >> 3;            // 0..15 (+16i, i=0..7)
    const int a_c = (tid & 7) * 4;       // float col base (16B chunk)
    const int bn_k = tid >> 5;           // 0..3 (+4i, i=0..7)
    const int bn_c = (tid & 31) * 4;

    float inv[8];
    if (NORM) {
#pragma unroll
        for (int i = 0; i < 8; i++)
            inv[i] = rs[blockIdx.z * S + m0 + a_r + 16 * i];
    }

    float acc[4][8][4];
#pragma unroll
    for (int mt = 0; mt < 4; mt++)
#pragma unroll
        for (int nt = 0; nt < 8; nt++)
#pragma unroll
            for (int i = 0; i < 4; i++) acc[mt][nt][i] = 0.0f;

    const int ktiles = K / BK;
    float4 pa[8];   // only used when NORM

    auto issueA = [&](int st, int kt) {
        const uint32_t as = sbase + st * STAGE_BYTES;
        const float* p = Ab + (long long)a_r * lda + kt * BK + a_c;
#pragma unroll
        for (int i = 0; i < 8; i++)
            cp16(as + (uint32_t)(((a_r + 16 * i) * AS_STRIDE + a_c) * 4),
                 p + (long long)(16 * i) * lda);
    };
    auto issueB = [&](int st, int kt) {
        const uint32_t bs = sbase + st * STAGE_BYTES + A_BYTES;
        if (TB) {
            const float* p = Bb + (long long)a_r * ldb + kt * BK + a_c;
#pragma unroll
            for (int i = 0; i < 8; i++)
                cp16(bs + (uint32_t)(((a_r + 16 * i) * AS_STRIDE + a_c) * 4),
                     p + (long long)(16 * i) * ldb);
        } else {
            const float* p = Bb + (long long)(kt * BK + bn_k) * ldb + bn_c;
#pragma unroll
            for (int i = 0; i < 8; i++)
                cp16(bs + (uint32_t)(((bn_k + 4 * i) * BS_STRIDE + bn_c) * 4),
                     p + (long long)(4 * i) * ldb);
        }
    };
    auto ldAreg = [&](int kt) {
        const float* p = Ab + (long long)a_r * lda + kt * BK + a_c;
#pragma unroll
        for (int i = 0; i < 8; i++)
            pa[i] = *(const float4*)(p + (long long)(16 * i) * lda);
    };
    // NORM: write e*inv to gmem (final attn), stage tf32(e) into smem
    auto stAnorm = [&](int st, int kt) {
        float* As = (float*)(smem + st * STAGE_BYTES);
#pragma unroll
        for (int i = 0; i < 8; i++) {
            float4 v = pa[i];
            float4 w;
            w.x = v.x * inv[i]; w.y = v.y * inv[i];
            w.z = v.z * inv[i]; w.w = v.w * inv[i];
            *(float4*)(Awb + (long long)(a_r + 16 * i) * lda + kt * BK + a_c) = w;
            float4 t;
            t.x = tf32f(v.x); t.y = tf32f(v.y); t.z = tf32f(v.z); t.w = tf32f(v.w);
            *(float4*)&As[(a_r + 16 * i) * AS_STRIDE + a_c] = t;
        }
    };

    // ---- prologue: fill stages 0,1 ----
#pragma unroll
    for (int s = 0; s < 2; s++) {
        if (!NORM) issueA(s, s);
        issueB(s, s);
        CP_COMMIT();
        if (NORM) { ldAreg(s); stAnorm(s, s); }
    }

    for (int kt = 0; kt < ktiles; kt++) {
        const int cur = kt % STAGES;
        const bool has = (kt + 2 < ktiles);
        if (has) CP_WAIT1(); else CP_WAIT0();
        __syncthreads();

        const int nx = (kt + 2) % STAGES;
        if (has) {
            if (!NORM) issueA(nx, kt + 2);
            issueB(nx, kt + 2);
            CP_COMMIT();
            if (NORM) ldAreg(kt + 2);
        }

        const uint32_t as_s = sbase + cur * STAGE_BYTES;
        const uint32_t bs_s = as_s + A_BYTES;
        const float* Bs = (const float*)(smem + cur * STAGE_BYTES + A_BYTES);

        // fragment double-buffer across the 4 ks steps
        unsigned af[2][4][4], bf[2][8][2];
        auto ldfrag = [&](int ks, int buf) {
            const int k = ks * 8;
            // A fragments: one ldmatrix.x4 per mt
#pragma unroll
            for (int mt = 0; mt < 4; mt++) {
                unsigned r[4];
                ldsm4(r, as_s + aoff + (uint32_t)(mt * 16 * AS_STRIDE * 4 + ks * 32));
                af[buf][mt][0] = CVA ? tf32u(r[0]) : r[0];
                af[buf][mt][1] = CVA ? tf32u(r[1]) : r[1];
                af[buf][mt][2] = CVA ? tf32u(r[2]) : r[2];
                af[buf][mt][3] = CVA ? tf32u(r[3]) : r[3];
            }
            if (TB) {
                // B fragments: one ldmatrix.x4 per nt-pair
#pragma unroll
                for (int np = 0; np < 4; np++) {
                    unsigned r[4];
                    ldsm4(r, bs_s + boff + (uint32_t)(np * 16 * AS_STRIDE * 4 + ks * 32));
                    bf[buf][2 * np][0]     = CVB ? tf32u(r[0]) : r[0];
                    bf[buf][2 * np][1]     = CVB ? tf32u(r[1]) : r[1];
                    bf[buf][2 * np + 1][0] = CVB ? tf32u(r[2]) : r[2];
                    bf[buf][2 * np + 1][1] = CVB ? tf32u(r[3]) : r[3];
                }
            } else {
#pragma unroll
                for (int nt = 0; nt < 8; nt++) {
                    const int c = wn + nt * 8 + lg;
                    unsigned v0 = __float_as_uint(Bs[(k + l4) * BS_STRIDE + c]);
                    unsigned v1 = __float_as_uint(Bs[(k + l4 + 4) * BS_STRIDE + c]);
                    bf[buf][nt][0] = CVB ? tf32u(v0) : v0;
                    bf[buf][nt][1] = CVB ? tf32u(v1) : v1;
                }
            }
        };

        ldfrag(0, 0);
#pragma unroll
        for (int ks = 0; ks < 4; ks++) {
            const int cb = ks & 1;
            if (ks < 3) ldfrag(ks + 1, cb ^ 1);
#pragma unroll
            for (int mt = 0; mt < 4; mt++)
#pragma unroll
                for (int nt = 0; nt < 8; nt++)
                    mma_tf32(acc[mt][nt], af[cb][mt], bf[cb][nt]);
        }

        if (has && NORM) stAnorm(nx, kt + 2);
    }

    // ---- epilogue ----
    if (EXPE) {
        float ps[4][2];
#pragma unroll
        for (int mt = 0; mt < 4; mt++) { ps[mt][0] = 0.0f; ps[mt][1] = 0.0f; }
#pragma unroll
        for (int mt = 0; mt < 4; mt++) {
            const int r = wm + mt * 16 + lg;
#pragma unroll
            for (int nt = 0; nt < 8; nt++) {
                const int c = wn + nt * 8 + 2 * l4;
                float e0 = __expf(acc[mt][nt][0] * alpha);
                float e1 = __expf(acc[mt][nt][1] * alpha);
                float e2 = __expf(acc[mt][nt][2] * alpha);
                float e3 = __expf(acc[mt][nt][3] * alpha);
                *(float2*)(Cb + (long long)r * ldc + c) = make_float2(e0, e1);
                *(float2*)(Cb + (long long)(r + 8) * ldc + c) = make_float2(e2, e3);
                ps[mt][0] += e0 + e1;
                ps[mt][1] += e2 + e3;
            }
        }
#pragma unroll
        for (int mt = 0; mt < 4; mt++) {
#pragma unroll
            for (int h = 0; h < 2; h++) {
                float v = ps[mt][h];
                v += __shfl_xor_sync(0xffffffffu, v, 1);
                v += __shfl_xor_sync(0xffffffffu, v, 2);
                if (l4 == 0)
                    atomicAdd(&rs[blockIdx.z * S + m0 + wm + mt * 16 + lg + h * 8], v);
            }
        }
    } else {
#pragma unroll
        for (int mt = 0; mt < 4; mt++) {
            const int r = wm + mt * 16 + lg;
            float s0 = alpha, s1 = alpha;
            if (NORM) {
                s0 = rs[blockIdx.z * S + m0 + r];
                s1 = rs[blockIdx.z * S + m0 + r + 8];
            }
#pragma unroll
            for (int nt = 0; nt < 8; nt++) {
                const int c = wn + nt * 8 + 2 * l4;
                float o0 = acc[mt][nt][0] * s0, o1 = acc[mt][nt][1] * s0;
                float o2 = acc[mt][nt][2] * s1, o3 = acc[mt][nt][3] * s1;
                if (ROUND) {
                    o0 = tf32f(o0); o1 = tf32f(o1);
                    o2 = tf32f(o2); o3 = tf32f(o3);
                }
                if (QKV3 && trc) {
                    // store transposed into Aw[H][S]: Aw[gc][gm]
                    const long long gm = m0 + r;
                    const int gc = n0 + c;
                    Aw[(long long)gc * S + gm]           = o0;
                    Aw[(long long)(gc + 1) * S + gm]     = o1;
                    Aw[(long long)gc * S + gm + 8]       = o2;
                    Aw[(long long)(gc + 1) * S + gm + 8] = o3;
                } else {
                    *(float2*)(Cb + (long long)r * ldc + c) = make_float2(o0, o1);
                    *(float2*)(Cb + (long long)(r + 8) * ldc + c) = make_float2(o2, o3);
                }
            }
        }
    }
}

__global__ void inv_rs(float* rs, int n) {
    int i = blockIdx.x * blockDim.x + threadIdx.x;
    if (i < n) rs[i] = 1.0f / rs[i];
}

extern "C" void kernel_launch(void* const* d_in, const int* in_sizes, int n_in,
                              void* d_out, int out_size)
{
    const float* x  = (const float*)d_in[0];
    const float* Wq = (const float*)d_in[1];
    const float* Wk = (const float*)d_in[2];
    const float* Wv = (const float*)d_in[3];
    const float* Wo = (const float*)d_in[4];

    const int F  = 1024;
    const int H  = 1024;
    const int NH = NHEAD;
    const int DK = H / NH;                 // 128
    const int S  = in_sizes[0] / F;        // 4096

    float* y_out    = (float*)d_out;
    float* attn_out = y_out + (long long)S * H;

    float *qkv, *vt, *y, *rs;
    cudaGetSymbolAddress((void**)&qkv, g_qkv);
    cudaGetSymbolAddress((void**)&vt, g_vt);
    cudaGetSymbolAddress((void**)&y, g_y);
    cudaGetSymbolAddress((void**)&rs, g_rs);
    float* q = qkv;
    float* k = qkv + (long long)S * H;

    // template args: TB, EXPE, NORM, CVA, CVB, ROUND, QKV3
    auto kQKV  = gemm_mha<false, false, false, true,  true,  true,  true >;
    auto kQKT  = gemm_mha<true,  true,  false, false, false, false, false>;
    auto kAV   = gemm_mha<true,  false, true,  false, false, true,  false>;
    auto kPROJ = gemm_mha<false, false, false, false, true,  false, false>;

    cudaFuncSetAttribute(kQKV,  cudaFuncAttributeMaxDynamicSharedMemorySize, SMEM_DYN);
    cudaFuncSetAttribute(kQKT,  cudaFuncAttributeMaxDynamicSharedMemorySize, SMEM_DYN);
    cudaFuncSetAttribute(kAV,   cudaFuncAttributeMaxDynamicSharedMemorySize, SMEM_DYN);
    cudaFuncSetAttribute(kPROJ, cudaFuncAttributeMaxDynamicSharedMemorySize, SMEM_DYN);

    const dim3 blk(NTHREADS);
    const float inv_sqrt_dk = 0.08838834764831845f;  // 1/sqrt(128)

    // 1) fused Q/K/V projections (+rs zeroing); v written transposed to g_vt
    dim3 g1(3 * (H / NT), S / MT, 1);
    kQKV<<<g1, blk, SMEM_DYN>>>(x, Wq, Wk, Wv, qkv, vt, rs,
                                F, F, H, H, 0, 0, (long long)S * H, 1.0f, S);

    // 2) logits -> exp(Q K^T / sqrt(dk)) fp32 into attn region + row sums
    dim3 g2(S / NT, S / MT, NH);
    kQKT<<<g2, blk, SMEM_DYN>>>(q, k, nullptr, nullptr, attn_out, nullptr, rs,
                                DK, H, H, S,
                                (long long)DK, (long long)DK, (long long)S * S,
                                inv_sqrt_dk, S);

    // 3) invert row sums
    inv_rs<<<(NH * S + 255) / 256, 256>>>(rs, NH * S);

    // 4) AV (TB, all-ldsm): Y = inv.(E @ Vt^T); loader writes normalized attn
    dim3 g3(DK / NT, S / MT, NH);
    kAV<<<g3, blk, SMEM_DYN>>>(attn_out, vt, nullptr, nullptr, y, attn_out, rs,
                               S, S, S, H,
                               (long long)S * S, (long long)DK * S, (long long)DK,
                               1.0f, S);

    // 5) output projection: y_out = Y @ Wo (fp32 out)
    dim3 g4(F / NT, S / MT, 1);
    kPROJ<<<g4, blk, SMEM_DYN>>>(y, Wo, nullptr, nullptr, y_out, nullptr, rs,
                                 H, H, F, F, 0, 0, 0, 1.0f, S);
}

// round 12
// speedup vs baseline: 1.2756x; 1.0635x over previous
#include <cuda_runtime.h>
#include <cstdint>
#include <math.h>

// ---------------------------------------------------------------------------
// MultiHeadAttention, tf32 mma.sync GEMMs, cp.async 3-stage pipelines,
// ldmatrix fragment loads, fused softmax, fused QKV (v stored transposed).
// AV normalizes attn from smem (no register staging, no spills).
// CTA 128x128x32, 4 warps (2x2 of 64x64 warp tiles), 2 CTAs/SM.
// d_out = y [S,F] then attn [8,S,S] (fp32). S=4096, F=H=1024, dk=128.
// ---------------------------------------------------------------------------

#define SMAX 4096
#define HMAX 1024
#define NHEAD 8

__device__ float g_qkv[3 * SMAX * HMAX];     // q | k | (v unused plane)
__device__ float g_vt[HMAX * SMAX];          // v transposed [H][S]
__device__ float g_y[SMAX * HMAX];
__device__ float g_rs[NHEAD * SMAX];         // raw row sums of exp

__device__ __forceinline__ unsigned tf32u(unsigned x) {
    unsigned r;
    asm("cvt.rna.tf32.f32 %0, %1;" : "=r"(r) : "f"(__uint_as_float(x)));
    return r;
}
__device__ __forceinline__ float tf32f(float x) {
    unsigned r;
    asm("cvt.rna.tf32.f32 %0, %1;" : "=r"(r) : "f"(x));
    return __uint_as_float(r);
}
__device__ __forceinline__ void mma_tf32(float* c, const unsigned* a, const unsigned* b) {
    asm volatile(
        "mma.sync.aligned.m16n8k8.row.col.f32.tf32.tf32.f32 "
        "{%0,%1,%2,%3}, {%4,%5,%6,%7}, {%8,%9}, {%0,%1,%2,%3};"
        : "+f"(c[0]), "+f"(c[1]), "+f"(c[2]), "+f"(c[3])
        : "r"(a[0]), "r"(a[1]), "r"(a[2]), "r"(a[3]), "r"(b[0]), "r"(b[1]));
}
__device__ __forceinline__ void ldsm4(unsigned* r, uint32_t a) {
    asm volatile("ldmatrix.sync.aligned.m8n8.x4.shared.b16 {%0,%1,%2,%3}, [%4];"
        : "=r"(r[0]), "=r"(r[1]), "=r"(r[2]), "=r"(r[3]) : "r"(a));
}
__device__ __forceinline__ uint32_t smem_u32(const void* p) {
    uint32_t a;
    asm("{ .reg .u64 t; cvta.to.shared.u64 t, %1; cvt.u32.u64 %0, t; }" : "=r"(a) : "l"(p));
    return a;
}
__device__ __forceinline__ void cp16(uint32_t s, const void* g) {
    asm volatile("cp.async.cg.shared.global [%0], [%1], 16;" :: "r"(s), "l"(g));
}
#define CP_COMMIT() asm volatile("cp.async.commit_group;")
#define CP_WAIT1()  asm volatile("cp.async.wait_group 1;")
#define CP_WAIT0()  asm volatile("cp.async.wait_group 0;")

// Tile config: CTA 128(M) x 128(N) x 32(K), 4 warps (2m x 2n), warp tile 64x64.
#define MT  128
#define NT  128
#define BK  32
#define STAGES 3
#define NTHREADS 128
#define AS_STRIDE 36      // floats; [m][k] and TB [n][k]
#define BS_STRIDE 136     // NN layout [k][n]
#define A_BYTES  (128 * AS_STRIDE * 4)           // 18432
#define B_BYTES  (128 * AS_STRIDE * 4)           // 18432 (covers NN 17408 too)
#define STAGE_BYTES (A_BYTES + B_BYTES)          // 36864
#define SMEM_DYN (STAGES * STAGE_BYTES)          // 110592  (x2 CTAs = 221184)

// ---------------------------------------------------------------------------
// TB=false: C = alpha * A[M,K] @ B[K,N]   (B row-major; Bs [k][n] stride 136)
// TB=true : C = alpha * A[M,K] @ B[N,K]^T (B K-major;   Bs [n][k] stride 36)
// EXPE : epilogue C = exp(alpha*acc) fp32, atomicAdd fp32 row sums into rs
// NORM : A = raw exp values E via cp.async; after each stage lands, the tile
//        is re-read from smem, scaled by 1/rs, and written to Aw (final attn).
//        Mainloop uses CVA (rna) on fragments; epilogue scales rows by 1/rs.
//        Fragments single-buffered (DRAM-bound; saves 32 regs -> 2 CTAs/SM).
// CVA/CVB : cvt.rna.tf32 on A/B fragments
// ROUND : round plain epilogue output to tf32 (when C feeds another GEMM)
// QKV3 : blockIdx.x = (bsel << 3) | n-tile; bsel 2 (v) stores transposed
//        into Aw as [H][S]; CTAs with blockIdx.x==0 zero rs.
// ---------------------------------------------------------------------------
template <bool TB, bool EXPE, bool NORM, bool CVA, bool CVB, bool ROUND, bool QKV3>
__global__ void __launch_bounds__(NTHREADS, 2) gemm_mha(
    const float* __restrict__ A, const float* __restrict__ B0,
    const float* __restrict__ B1, const float* __restrict__ B2,
    float* __restrict__ C, float* __restrict__ Aw, float* __restrict__ rs,
    int K, int lda, int ldb, int ldc,
    long long sA, long long sB, long long sC, float alpha, int S)
{
    extern __shared__ char smem[];
    const uint32_t sbase = smem_u32(smem);
    const int tid = threadIdx.x;
    const int lane = tid & 31;
    const int warp = tid >> 5;
    const int lg = lane >> 2;          // 0..7
    const int l4 = lane & 3;           // 0..3
    const int wm = (warp & 1) * 64;    // 2 m-warps
    const int wn = (warp >> 1) * 64;   // 2 n-warps

    // ldmatrix lane offsets (bytes, relative to tile base)
    const int lgp = lane >> 3, ri = lane & 7;
    const uint32_t aoff = (uint32_t)((wm + ((lgp & 1) << 3) + ri) * (AS_STRIDE * 4)
                                     + ((lgp >> 1) << 4));
    const uint32_t boff = (uint32_t)((wn + ((lgp >> 1) << 3) + ri) * (AS_STRIDE * 4)
                                     + ((lgp & 1) << 4));   // TB layout only

    const int m0 = blockIdx.y * MT;
    int n0;
    const float* B;
    float* Cm;
    bool trc = false;
    if (QKV3) {
        const int bsel = blockIdx.x >> 3;
        n0 = (blockIdx.x & 7) * NT;
        B = (bsel == 0) ? B0 : ((bsel == 1) ? B1 : B2);
        Cm = C + (long long)bsel * sC;
        trc = (bsel == 2);
        if (blockIdx.x == 0) {
            float4 z = make_float4(0.f, 0.f, 0.f, 0.f);
            float* p = rs + blockIdx.y * (NHEAD * S / 32) + tid * 8;
            *(float4*)p = z;
            *(float4*)(p + 4) = z;
        }
    } else {
        n0 = blockIdx.x * NT;
        B = B0;
        Cm = C + (long long)blockIdx.z * sC;
    }

    const float* Ab = A + (long long)blockIdx.z * sA + (long long)m0 * lda;
    float* Awb = NORM ? (Aw + (long long)blockIdx.z * sA + (long long)m0 * lda) : nullptr;
    const float* Bb;
    if (TB) Bb = B + (long long)blockIdx.z * sB + (long long)n0 * ldb;
    else    Bb = B + (long long)blockIdx.z * sB + n0;
    float* Cb = Cm + (long long)m0 * ldc + n0;

    // loader mappings (128 threads)
    const int a_r = tid >> 3;            // 0..15 (+16i, i=0..7)
    const int a_c = (tid & 7) * 4;       // float col base (16B chunk)
    const int bn_k = tid >> 5;           // 0..3 (+4i, i=0..7)
    const int bn_c = (tid & 31) * 4;

    float inv[8];
    if (NORM) {
#pragma unroll
        for (int i = 0; i < 8; i++)
            inv[i] = 1.0f / rs[blockIdx.z * S + m0 + a_r + 16 * i];
    }

    float acc[4][8][4];
#pragma unroll
    for (int mt = 0; mt < 4; mt++)
#pragma unroll
        for (int nt = 0; nt < 8; nt++)
#pragma unroll
            for (int i = 0; i < 4; i++) acc[mt][nt][i] = 0.0f;

    const int ktiles = K / BK;

    auto issueA = [&](int st, int kt) {
        const uint32_t as = sbase + st * STAGE_BYTES;
        const float* p = Ab + (long long)a_r * lda + kt * BK + a_c;
#pragma unroll
        for (int i = 0; i < 8; i++)
            cp16(as + (uint32_t)(((a_r + 16 * i) * AS_STRIDE + a_c) * 4),
                 p + (long long)(16 * i) * lda);
    };
    auto issueB = [&](int st, int kt) {
        const uint32_t bs = sbase + st * STAGE_BYTES + A_BYTES;
        if (TB) {
            const float* p = Bb + (long long)a_r * ldb + kt * BK + a_c;
#pragma unroll
            for (int i = 0; i < 8; i++)
                cp16(bs + (uint32_t)(((a_r + 16 * i) * AS_STRIDE + a_c) * 4),
                     p + (long long)(16 * i) * ldb);
        } else {
            const float* p = Bb + (long long)(kt * BK + bn_k) * ldb + bn_c;
#pragma unroll
            for (int i = 0; i < 8; i++)
                cp16(bs + (uint32_t)(((bn_k + 4 * i) * BS_STRIDE + bn_c) * 4),
                     p + (long long)(4 * i) * ldb);
        }
    };
    // NORM: read raw E tile from smem, scale by 1/rs, write final attn to gmem
    auto wrNorm = [&](int st, int kt) {
        const float* As = (const float*)(smem + st * STAGE_BYTES);
#pragma unroll
        for (int i = 0; i < 8; i++) {
            float4 v = *(const float4*)&As[(a_r + 16 * i) * AS_STRIDE + a_c];
            v.x *= inv[i]; v.y *= inv[i]; v.z *= inv[i]; v.w *= inv[i];
            *(float4*)(Awb + (long long)(a_r + 16 * i) * lda + kt * BK + a_c) = v;
        }
    };

    // ---- prologue: fill stages 0,1 ----
#pragma unroll
    for (int s = 0; s < 2; s++) {
        issueA(s, s);
        issueB(s, s);
        CP_COMMIT();
    }

    for (int kt = 0; kt < ktiles; kt++) {
        const int cur = kt % STAGES;
        const bool has = (kt + 2 < ktiles);
        if (has) CP_WAIT1(); else CP_WAIT0();
        __syncthreads();

        const int nx = (kt + 2) % STAGES;
        if (has) {
            issueA(nx, kt + 2);
            issueB(nx, kt + 2);
            CP_COMMIT();
        }

        if (NORM) wrNorm(cur, kt);

        const uint32_t as_s = sbase + cur * STAGE_BYTES;
        const uint32_t bs_s = as_s + A_BYTES;
        const float* Bs = (const float*)(smem + cur * STAGE_BYTES + A_BYTES);

        if (NORM) {
            // single-buffered fragments (DRAM-bound; save registers)
#pragma unroll
            for (int ks = 0; ks < 4; ks++) {
                unsigned af[4][4], bf[8][2];
#pragma unroll
                for (int mt = 0; mt < 4; mt++) {
                    unsigned r[4];
                    ldsm4(r, as_s + aoff + (uint32_t)(mt * 16 * AS_STRIDE * 4 + ks * 32));
                    af[mt][0] = CVA ? tf32u(r[0]) : r[0];
                    af[mt][1] = CVA ? tf32u(r[1]) : r[1];
                    af[mt][2] = CVA ? tf32u(r[2]) : r[2];
                    af[mt][3] = CVA ? tf32u(r[3]) : r[3];
                }
#pragma unroll
                for (int np = 0; np < 4; np++) {
                    unsigned r[4];
                    ldsm4(r, bs_s + boff + (uint32_t)(np * 16 * AS_STRIDE * 4 + ks * 32));
                    bf[2 * np][0]     = CVB ? tf32u(r[0]) : r[0];
                    bf[2 * np][1]     = CVB ? tf32u(r[1]) : r[1];
                    bf[2 * np + 1][0] = CVB ? tf32u(r[2]) : r[2];
                    bf[2 * np + 1][1] = CVB ? tf32u(r[3]) : r[3];
                }
#pragma unroll
                for (int mt = 0; mt < 4; mt++)
#pragma unroll
                    for (int nt = 0; nt < 8; nt++)
                        mma_tf32(acc[mt][nt], af[mt], bf[nt]);
            }
        } else {
            // double-buffered fragments (tensor-bound path)
            unsigned af[2][4][4], bf[2][8][2];
            auto ldfrag = [&](int ks, int buf) {
                const int k = ks * 8;
#pragma unroll
                for (int mt = 0; mt < 4; mt++) {
                    unsigned r[4];
                    ldsm4(r, as_s + aoff + (uint32_t)(mt * 16 * AS_STRIDE * 4 + ks * 32));
                    af[buf][mt][0] = CVA ? tf32u(r[0]) : r[0];
                    af[buf][mt][1] = CVA ? tf32u(r[1]) : r[1];
                    af[buf][mt][2] = CVA ? tf32u(r[2]) : r[2];
                    af[buf][mt][3] = CVA ? tf32u(r[3]) : r[3];
                }
                if (TB) {
#pragma unroll
                    for (int np = 0; np < 4; np++) {
                        unsigned r[4];
                        ldsm4(r, bs_s + boff + (uint32_t)(np * 16 * AS_STRIDE * 4 + ks * 32));
                        bf[buf][2 * np][0]     = CVB ? tf32u(r[0]) : r[0];
                        bf[buf][2 * np][1]     = CVB ? tf32u(r[1]) : r[1];
                        bf[buf][2 * np + 1][0] = CVB ? tf32u(r[2]) : r[2];
                        bf[buf][2 * np + 1][1] = CVB ? tf32u(r[3]) : r[3];
                    }
                } else {
#pragma unroll
                    for (int nt = 0; nt < 8; nt++) {
                        const int c = wn + nt * 8 + lg;
                        unsigned v0 = __float_as_uint(Bs[(k + l4) * BS_STRIDE + c]);
                        unsigned v1 = __float_as_uint(Bs[(k + l4 + 4) * BS_STRIDE + c]);
                        bf[buf][nt][0] = CVB ? tf32u(v0) : v0;
                        bf[buf][nt][1] = CVB ? tf32u(v1) : v1;
                    }
                }
            };

            ldfrag(0, 0);
#pragma unroll
            for (int ks = 0; ks < 4; ks++) {
                const int cb = ks & 1;
                if (ks < 3) ldfrag(ks + 1, cb ^ 1);
#pragma unroll
                for (int mt = 0; mt < 4; mt++)
#pragma unroll
                    for (int nt = 0; nt < 8; nt++)
                        mma_tf32(acc[mt][nt], af[cb][mt], bf[cb][nt]);
            }
        }
    }

    // ---- epilogue ----
    if (EXPE) {
        float ps[4][2];
#pragma unroll
        for (int mt = 0; mt < 4; mt++) { ps[mt][0] = 0.0f; ps[mt][1] = 0.0f; }
#pragma unroll
        for (int mt = 0; mt < 4; mt++) {
            const int r = wm + mt * 16 + lg;
#pragma unroll
            for (int nt = 0; nt < 8; nt++) {
                const int c = wn + nt * 8 + 2 * l4;
                float e0 = __expf(acc[mt][nt][0] * alpha);
                float e1 = __expf(acc[mt][nt][1] * alpha);
                float e2 = __expf(acc[mt][nt][2] * alpha);
                float e3 = __expf(acc[mt][nt][3] * alpha);
                *(float2*)(Cb + (long long)r * ldc + c) = make_float2(e0, e1);
                *(float2*)(Cb + (long long)(r + 8) * ldc + c) = make_float2(e2, e3);
                ps[mt][0] += e0 + e1;
                ps[mt][1] += e2 + e3;
            }
        }
#pragma unroll
        for (int mt = 0; mt < 4; mt++) {
#pragma unroll
            for (int h = 0; h < 2; h++) {
                float v = ps[mt][h];
                v += __shfl_xor_sync(0xffffffffu, v, 1);
                v += __shfl_xor_sync(0xffffffffu, v, 2);
                if (l4 == 0)
                    atomicAdd(&rs[blockIdx.z * S + m0 + wm + mt * 16 + lg + h * 8], v);
            }
        }
    } else {
#pragma unroll
        for (int mt = 0; mt < 4; mt++) {
            const int r = wm + mt * 16 + lg;
            float s0 = alpha, s1 = alpha;
            if (NORM) {
                s0 = 1.0f / rs[blockIdx.z * S + m0 + r];
                s1 = 1.0f / rs[blockIdx.z * S + m0 + r + 8];
            }
#pragma unroll
            for (int nt = 0; nt < 8; nt++) {
                const int c = wn + nt * 8 + 2 * l4;
                float o0 = acc[mt][nt][0] * s0, o1 = acc[mt][nt][1] * s0;
                float o2 = acc[mt][nt][2] * s1, o3 = acc[mt][nt][3] * s1;
                if (ROUND) {
                    o0 = tf32f(o0); o1 = tf32f(o1);
                    o2 = tf32f(o2); o3 = tf32f(o3);
                }
                if (QKV3 && trc) {
                    const long long gm = m0 + r;
                    const int gc = n0 + c;
                    Aw[(long long)gc * S + gm]           = o0;
                    Aw[(long long)(gc + 1) * S + gm]     = o1;
                    Aw[(long long)gc * S + gm + 8]       = o2;
                    Aw[(long long)(gc + 1) * S + gm + 8] = o3;
                } else {
                    *(float2*)(Cb + (long long)r * ldc + c) = make_float2(o0, o1);
                    *(float2*)(Cb + (long long)(r + 8) * ldc + c) = make_float2(o2, o3);
                }
            }
        }
    }
}

extern "C" void kernel_launch(void* const* d_in, const int* in_sizes, int n_in,
                              void* d_out, int out_size)
{
    const float* x  = (const float*)d_in[0];
    const float* Wq = (const float*)d_in[1];
    const float* Wk = (const float*)d_in[2];
    const float* Wv = (const float*)d_in[3];
    const float* Wo = (const float*)d_in[4];

    const int F  = 1024;
    const int H  = 1024;
    const int NH = NHEAD;
    const int DK = H / NH;                 // 128
    const int S  = in_sizes[0] / F;        // 4096

    float* y_out    = (float*)d_out;
    float* attn_out = y_out + (long long)S * H;

    float *qkv, *vt, *y, *rs;
    cudaGetSymbolAddress((void**)&qkv, g_qkv);
    cudaGetSymbolAddress((void**)&vt, g_vt);
    cudaGetSymbolAddress((void**)&y, g_y);
    cudaGetSymbolAddress((void**)&rs, g_rs);
    float* q = qkv;
    float* k = qkv + (long long)S * H;

    // template args: TB, EXPE, NORM, CVA, CVB, ROUND, QKV3
    auto kQKV  = gemm_mha<false, false, false, true,  true,  true,  true >;
    auto kQKT  = gemm_mha<true,  true,  false, false, false, false, false>;
    auto kAV   = gemm_mha<true,  false, true,  true,  false, true,  false>;
    auto kPROJ = gemm_mha<false, false, false, false, true,  false, false>;

    cudaFuncSetAttribute(kQKV,  cudaFuncAttributeMaxDynamicSharedMemorySize, SMEM_DYN);
    cudaFuncSetAttribute(kQKT,  cudaFuncAttributeMaxDynamicSharedMemorySize, SMEM_DYN);
    cudaFuncSetAttribute(kAV,   cudaFuncAttributeMaxDynamicSharedMemorySize, SMEM_DYN);
    cudaFuncSetAttribute(kPROJ, cudaFuncAttributeMaxDynamicSharedMemorySize, SMEM_DYN);

    const dim3 blk(NTHREADS);
    const float inv_sqrt_dk = 0.08838834764831845f;  // 1/sqrt(128)

    // 1) fused Q/K/V projections (+rs zeroing); v written transposed to g_vt
    dim3 g1(3 * (H / NT), S / MT, 1);
    kQKV<<<g1, blk, SMEM_DYN>>>(x, Wq, Wk, Wv, qkv, vt, rs,
                                F, F, H, H, 0, 0, (long long)S * H, 1.0f, S);

    // 2) logits -> exp(Q K^T / sqrt(dk)) fp32 into attn region + raw row sums
    dim3 g2(S / NT, S / MT, NH);
    kQKT<<<g2, blk, SMEM_DYN>>>(q, k, nullptr, nullptr, attn_out, nullptr, rs,
                                DK, H, H, S,
                                (long long)DK, (long long)DK, (long long)S * S,
                                inv_sqrt_dk, S);

    // 3) AV (TB, all-ldsm): Y = (E @ Vt^T)/rs; writes normalized attn from smem
    dim3 g3(DK / NT, S / MT, NH);
    kAV<<<g3, blk, SMEM_DYN>>>(attn_out, vt, nullptr, nullptr, y, attn_out, rs,
                               S, S, S, H,
                               (long long)S * S, (long long)DK * S, (long long)DK,
                               1.0f, S);

    // 4) output projection: y_out = Y @ Wo (fp32 out)
    dim3 g4(F / NT, S / MT, 1);
    kPROJ<<<g4, blk, SMEM_DYN>>>(y, Wo, nullptr, nullptr, y_out, nullptr, rs,
                                 H, H, F, F, 0, 0, 0, 1.0f, S);
}